// round 1
// baseline (speedup 1.0000x reference)
#include <cuda_runtime.h>
#include <math.h>

#define DD    1024
#define MB    16384          // B*S
#define CHUNK 64

// ---------------- scratch (static device arrays; no allocation) ----------------
__device__ float g_key[MB * DD];
__device__ float g_val[MB * DD];
__device__ float g_qry[MB * DD];
__device__ float g_kp [MB * DD];
__device__ float g_qp [MB * DD];
__device__ float g_ln [MB * DD];

// ---------------- GEMM: C[m,n] = sum_k A[m,k] * W[n,k] (+ epilogue) ------------
// MODE 0: C = A@W^T + bias
// MODE 1: C = tanh(A@W^T + bias) * extra[n]        (extra = phase_scale)
// MODE 2: C = A@W^T + bias + extra[m*DD+n]         (extra = residual x)
template<int MODE>
__global__ void __launch_bounds__(256, 2)
gemm_nt(const float* __restrict__ A, const float* __restrict__ W,
        const float* __restrict__ bias, const float* __restrict__ extra,
        float* __restrict__ C)
{
    __shared__ float As[2][8][128];
    __shared__ float Bs[2][8][128];

    const int tid = threadIdx.x;
    const int bm  = blockIdx.y << 7;      // M tile origin
    const int bn  = blockIdx.x << 7;      // N tile origin
    const int lr  = tid >> 1;             // 0..127 : row within tile being loaded
    const int lk  = (tid & 1) << 2;       // 0 or 4 : k offset of float4

    const float* Ap = A + (size_t)(bm + lr) * DD + lk;
    const float* Wp = W + (size_t)(bn + lr) * DD + lk;

    float acc[8][8];
#pragma unroll
    for (int i = 0; i < 8; i++)
#pragma unroll
        for (int j = 0; j < 8; j++) acc[i][j] = 0.f;

    // prologue: stage k-tile 0
    float4 a4 = *(const float4*)Ap;
    float4 w4 = *(const float4*)Wp;
#pragma unroll
    for (int j = 0; j < 4; j++) {
        As[0][lk + j][lr] = ((const float*)&a4)[j];
        Bs[0][lk + j][lr] = ((const float*)&w4)[j];
    }
    __syncthreads();

    const int tm = (tid >> 4) << 3;  // 0..120
    const int tn = (tid & 15) << 3;  // 0..120

    int cur = 0;
    const int NKT = DD / 8;
    for (int kt = 0; kt < NKT; kt++) {
        if (kt + 1 < NKT) {
            a4 = *(const float4*)(Ap + (size_t)(kt + 1) * 8);
            w4 = *(const float4*)(Wp + (size_t)(kt + 1) * 8);
        }
#pragma unroll
        for (int k = 0; k < 8; k++) {
            float ar[8], br[8];
            *(float4*)&ar[0] = *(const float4*)&As[cur][k][tm];
            *(float4*)&ar[4] = *(const float4*)&As[cur][k][tm + 4];
            *(float4*)&br[0] = *(const float4*)&Bs[cur][k][tn];
            *(float4*)&br[4] = *(const float4*)&Bs[cur][k][tn + 4];
#pragma unroll
            for (int i = 0; i < 8; i++)
#pragma unroll
                for (int j = 0; j < 8; j++)
                    acc[i][j] = fmaf(ar[i], br[j], acc[i][j]);
        }
        if (kt + 1 < NKT) {
#pragma unroll
            for (int j = 0; j < 4; j++) {
                As[cur ^ 1][lk + j][lr] = ((const float*)&a4)[j];
                Bs[cur ^ 1][lk + j][lr] = ((const float*)&w4)[j];
            }
            __syncthreads();
            cur ^= 1;
        }
    }

    // epilogue
    float bv[8], pv[8];
#pragma unroll
    for (int j = 0; j < 8; j++) bv[j] = bias[bn + tn + j];
    if (MODE == 1) {
#pragma unroll
        for (int j = 0; j < 8; j++) pv[j] = extra[bn + tn + j];
    }
#pragma unroll
    for (int i = 0; i < 8; i++) {
        const size_t row = (size_t)(bm + tm + i);
        float o[8];
#pragma unroll
        for (int j = 0; j < 8; j++) {
            float v = acc[i][j] + bv[j];
            if (MODE == 1) v = tanhf(v) * pv[j];
            o[j] = v;
        }
        if (MODE == 2) {
            const float* rp = extra + row * DD + bn + tn;
#pragma unroll
            for (int j = 0; j < 8; j++) o[j] += rp[j];
        }
        float* cp = C + row * DD + bn + tn;
        *(float4*)cp       = make_float4(o[0], o[1], o[2], o[3]);
        *(float4*)(cp + 4) = make_float4(o[4], o[5], o[6], o[7]);
    }
}

// ------------- fused bind + intra-chunk cumsum + retrieve + layernorm ----------
// One block per (batch, chunk): 1024 threads, thread t owns dim column t.
// Sequential scan over the 64 rows; per-row block reduction for layernorm.
__global__ void __launch_bounds__(1024)
scan_ln(const float* __restrict__ val, const float* __restrict__ kp,
        const float* __restrict__ qp, const float* __restrict__ lng,
        const float* __restrict__ lnb, float* __restrict__ outp)
{
    __shared__ float rs[32], rs2[32];
    __shared__ float s_mu, s_rstd;

    const int d    = threadIdx.x;
    const int lane = d & 31;
    const int wid  = d >> 5;
    const size_t base = (size_t)blockIdx.x * CHUNK * DD + d;
    const float gd = lng[d], bd = lnb[d];

    float ar = 0.f, ai = 0.f;
    for (int r = 0; r < CHUNK; r++) {
        const size_t idx = base + (size_t)r * DD;
        const float v  = val[idx];
        const float pk = kp[idx];
        const float pq = qp[idx];
        float sk, ck, sq, cq;
        sincosf(pk, &sk, &ck);
        sincosf(pq, &sq, &cq);
        ar = fmaf(v, ck, ar);
        ai = fmaf(v, sk, ai);
        const float x = (ar * cq + ai * sq) * 0.03125f;   // / sqrt(1024)

        // block reduction: sum and sum of squares over the 1024 dims
        float s = x, s2 = x * x;
#pragma unroll
        for (int o = 16; o; o >>= 1) {
            s  += __shfl_xor_sync(0xffffffffu, s,  o);
            s2 += __shfl_xor_sync(0xffffffffu, s2, o);
        }
        if (lane == 0) { rs[wid] = s; rs2[wid] = s2; }
        __syncthreads();
        if (wid == 0) {
            s  = rs[lane];
            s2 = rs2[lane];
#pragma unroll
            for (int o = 16; o; o >>= 1) {
                s  += __shfl_xor_sync(0xffffffffu, s,  o);
                s2 += __shfl_xor_sync(0xffffffffu, s2, o);
            }
            if (lane == 0) {
                const float mu  = s * (1.f / DD);
                const float var = s2 * (1.f / DD) - mu * mu;
                s_mu   = mu;
                s_rstd = rsqrtf(var + 1e-5f);
            }
        }
        __syncthreads();
        outp[idx] = (x - s_mu) * s_rstd * gd + bd;
    }
}

// --------------------------------- launch --------------------------------------
extern "C" void kernel_launch(void* const* d_in, const int* in_sizes, int n_in,
                              void* d_out, int out_size)
{
    const float* x   = (const float*)d_in[0];
    const float* Wk  = (const float*)d_in[1];
    const float* bk  = (const float*)d_in[2];
    const float* Wv  = (const float*)d_in[3];
    const float* bv  = (const float*)d_in[4];
    const float* Wq  = (const float*)d_in[5];
    const float* bq  = (const float*)d_in[6];
    const float* Wkp = (const float*)d_in[7];
    const float* bkp = (const float*)d_in[8];
    const float* Wqp = (const float*)d_in[9];
    const float* bqp = (const float*)d_in[10];
    const float* ps  = (const float*)d_in[11];
    const float* lng = (const float*)d_in[12];
    const float* lnb = (const float*)d_in[13];
    const float* Wo  = (const float*)d_in[14];
    const float* bo  = (const float*)d_in[15];
    float* out = (float*)d_out;

    float *pkey, *pval, *pqry, *pkp, *pqp, *pln;
    cudaGetSymbolAddress((void**)&pkey, g_key);
    cudaGetSymbolAddress((void**)&pval, g_val);
    cudaGetSymbolAddress((void**)&pqry, g_qry);
    cudaGetSymbolAddress((void**)&pkp,  g_kp);
    cudaGetSymbolAddress((void**)&pqp,  g_qp);
    cudaGetSymbolAddress((void**)&pln,  g_ln);

    dim3 grid(DD / 128, MB / 128);   // (8, 128)

    // K/V/Q projections
    gemm_nt<0><<<grid, 256>>>(x, Wk, bk, nullptr, pkey);
    gemm_nt<0><<<grid, 256>>>(x, Wv, bv, nullptr, pval);
    gemm_nt<0><<<grid, 256>>>(x, Wq, bq, nullptr, pqry);
    // phase projections (tanh * phase_scale fused)
    gemm_nt<1><<<grid, 256>>>(pkey, Wkp, bkp, ps, pkp);
    gemm_nt<1><<<grid, 256>>>(pqry, Wqp, bqp, ps, pqp);
    // bind + chunked cumsum + retrieve + layernorm
    scan_ln<<<MB / CHUNK, 1024>>>(pval, pkp, pqp, lng, lnb, pln);
    // output projection + residual
    gemm_nt<2><<<grid, 256>>>(pln, Wo, bo, x, out);
}

// round 3
// speedup vs baseline: 2.4407x; 2.4407x over previous
#include <cuda_runtime.h>
#include <cuda_fp16.h>
#include <math.h>
#include <stdint.h>

#define DD    1024
#define MB    16384
#define CHUNK 64
#define NKC   16            // K chunks of 64
#define STAGE 65536u        // Ah(16K) Al(16K) Wh(16K) Wl(16K)
#define SMEM_BYTES (2u * STAGE)

// ---------------- scratch (static device arrays; no allocation) ----------------
__device__ float g_key[MB * DD];
__device__ float g_val[MB * DD];
__device__ float g_qry[MB * DD];
__device__ float g_kp [MB * DD];
__device__ float g_qp [MB * DD];
__device__ float g_ln [MB * DD];

// ---------------- helpers ----------------
__device__ __forceinline__ uint32_t smem_u32(const void* p) {
    uint32_t a;
    asm("{ .reg .u64 t; cvta.to.shared.u64 t, %1; cvt.u32.u64 %0, t; }" : "=r"(a) : "l"(p));
    return a;
}
__device__ __forceinline__ void ldsm4(uint32_t* r, uint32_t addr) {
    asm volatile("ldmatrix.sync.aligned.m8n8.x4.shared.b16 {%0,%1,%2,%3}, [%4];"
                 : "=r"(r[0]), "=r"(r[1]), "=r"(r[2]), "=r"(r[3]) : "r"(addr));
}
__device__ __forceinline__ void mma16816(float* c, const uint32_t* a, uint32_t b0, uint32_t b1) {
    asm volatile(
        "mma.sync.aligned.m16n8k16.row.col.f32.f16.f16.f32 "
        "{%0,%1,%2,%3}, {%4,%5,%6,%7}, {%8,%9}, {%0,%1,%2,%3};"
        : "+f"(c[0]), "+f"(c[1]), "+f"(c[2]), "+f"(c[3])
        : "r"(a[0]), "r"(a[1]), "r"(a[2]), "r"(a[3]), "r"(b0), "r"(b1));
}
// split float4 into hi(fp16x4) + lo(fp16x4), hi+lo ~= fp32
__device__ __forceinline__ void split4(float4 v, uint2& h, uint2& l) {
    __half2 h0 = __floats2half2_rn(v.x, v.y);
    __half2 h1 = __floats2half2_rn(v.z, v.w);
    float2 f0 = __half22float2(h0);
    float2 f1 = __half22float2(h1);
    __half2 l0 = __floats2half2_rn(v.x - f0.x, v.y - f0.y);
    __half2 l1 = __floats2half2_rn(v.z - f1.x, v.w - f1.y);
    h.x = *(uint32_t*)&h0; h.y = *(uint32_t*)&h1;
    l.x = *(uint32_t*)&l0; l.y = *(uint32_t*)&l1;
}

// ---------------- 3xFP16 mma.sync GEMM: C[128,128] tile = A @ W^T + epilogue ---
// MODE 0: C = A@W^T + bias
// MODE 1: C = tanh(A@W^T + bias) * extra[n]
// MODE 2: C = A@W^T + bias + extra[row, n]     (residual)
template<int MODE>
__global__ void __launch_bounds__(256, 1)
gemm_mma(const float* __restrict__ A0, const float* __restrict__ A1, const float* __restrict__ A2,
         const float* __restrict__ W0, const float* __restrict__ W1, const float* __restrict__ W2,
         const float* __restrict__ b0, const float* __restrict__ b1, const float* __restrict__ b2,
         const float* __restrict__ extra,
         float* __restrict__ C0, float* __restrict__ C1, float* __restrict__ C2)
{
    extern __shared__ char smem[];
    const int tid = threadIdx.x;
    const int z   = blockIdx.z;
    const float* A    = (z == 0) ? A0 : (z == 1) ? A1 : A2;
    const float* W    = (z == 0) ? W0 : (z == 1) ? W1 : W2;
    const float* bias = (z == 0) ? b0 : (z == 1) ? b1 : b2;
    float*       C    = (z == 0) ? C0 : (z == 1) ? C1 : C2;

    const int bm = blockIdx.y << 7;
    const int bn = blockIdx.x << 7;

    const uint32_t sbu = smem_u32(smem);

    // ---- loader mapping: 2048 float4 per (A|W) chunk, 8 each per thread ----
    // idx = tid + i*256 ; row = idx>>4 (0..127) ; c4 = idx&15 (float4 within 64-k row)
    int lrow[8], lc4[8];
    uint32_t soff[8];
#pragma unroll
    for (int i = 0; i < 8; i++) {
        int idx = tid + (i << 8);
        lrow[i] = idx >> 4;
        lc4[i]  = idx & 15;
        soff[i] = (uint32_t)(lrow[i] * 128) + (uint32_t)((lc4[i] * 8) ^ ((lrow[i] & 7) << 4));
    }
    const float* ApB = A + (size_t)bm * DD;
    const float* WpB = W + (size_t)bn * DD;

    float4 ra[8], rw[8];
    auto ldg_chunk = [&](int kt) {
        const int kof = kt * 64;
#pragma unroll
        for (int i = 0; i < 8; i++)
            ra[i] = *(const float4*)(ApB + (size_t)lrow[i] * DD + kof + lc4[i] * 4);
#pragma unroll
        for (int i = 0; i < 8; i++)
            rw[i] = *(const float4*)(WpB + (size_t)lrow[i] * DD + kof + lc4[i] * 4);
    };
    auto sts_chunk = [&](int s) {
        char* base = smem + (uint32_t)s * STAGE;
#pragma unroll
        for (int i = 0; i < 8; i++) {
            uint2 h, l;
            split4(ra[i], h, l);
            *(uint2*)(base +          soff[i]) = h;
            *(uint2*)(base + 16384u + soff[i]) = l;
        }
#pragma unroll
        for (int i = 0; i < 8; i++) {
            uint2 h, l;
            split4(rw[i], h, l);
            *(uint2*)(base + 32768u + soff[i]) = h;
            *(uint2*)(base + 49152u + soff[i]) = l;
        }
    };

    // ---- warp compute mapping ----
    const int warp = tid >> 5, lane = tid & 31;
    const int warp_m0 = (warp >> 2) * 64;   // 2 warp rows
    const int warp_n0 = (warp & 3) * 32;    // 4 warp cols
    const int lr   = lane & 15;             // ldmatrix row-within-16
    const uint32_t lc   = (uint32_t)(lane >> 4) * 16;  // byte col-half
    const uint32_t xorv = (uint32_t)(lane & 7) << 4;

    float acc[4][4][4];
#pragma unroll
    for (int mi = 0; mi < 4; mi++)
#pragma unroll
        for (int ni = 0; ni < 4; ni++)
#pragma unroll
            for (int q = 0; q < 4; q++) acc[mi][ni][q] = 0.f;

    auto compute_chunk = [&](int s) {
        const uint32_t sA = sbu + (uint32_t)s * STAGE;
        const uint32_t sW = sA + 32768u;
#pragma unroll
        for (int kk = 0; kk < 4; kk++) {
            const uint32_t koff = ((uint32_t)(kk * 32) + lc) ^ xorv;
            uint32_t ah[4][4], al[4][4], wh[2][4], wl[2][4];
#pragma unroll
            for (int mi = 0; mi < 4; mi++) {
                const uint32_t rb = (uint32_t)((warp_m0 + mi * 16 + lr) * 128) + koff;
                ldsm4(ah[mi], sA + rb);
                ldsm4(al[mi], sA + 16384u + rb);
            }
#pragma unroll
            for (int g = 0; g < 2; g++) {
                const uint32_t rb = (uint32_t)((warp_n0 + g * 16 + lr) * 128) + koff;
                ldsm4(wh[g], sW + rb);
                ldsm4(wl[g], sW + 16384u + rb);
            }
#pragma unroll
            for (int mi = 0; mi < 4; mi++)
#pragma unroll
                for (int ni = 0; ni < 4; ni++) {
                    const uint32_t* bgrp = wh[ni >> 1];
                    mma16816(acc[mi][ni], ah[mi], bgrp[ni & 1], bgrp[(ni & 1) + 2]);
                }
#pragma unroll
            for (int mi = 0; mi < 4; mi++)
#pragma unroll
                for (int ni = 0; ni < 4; ni++) {
                    const uint32_t* bgrp = wh[ni >> 1];
                    mma16816(acc[mi][ni], al[mi], bgrp[ni & 1], bgrp[(ni & 1) + 2]);
                }
#pragma unroll
            for (int mi = 0; mi < 4; mi++)
#pragma unroll
                for (int ni = 0; ni < 4; ni++) {
                    const uint32_t* bgrp = wl[ni >> 1];
                    mma16816(acc[mi][ni], ah[mi], bgrp[ni & 1], bgrp[(ni & 1) + 2]);
                }
        }
    };

    // ---- pipeline ----
    ldg_chunk(0);
    sts_chunk(0);
    ldg_chunk(1);
    __syncthreads();
#pragma unroll 1
    for (int kt = 0; kt < NKC; kt++) {
        if (kt + 1 < NKC) sts_chunk((kt + 1) & 1);
        if (kt + 2 < NKC) ldg_chunk(kt + 2);
        compute_chunk(kt & 1);
        __syncthreads();
    }

    // ---- epilogue ----
#pragma unroll
    for (int ni = 0; ni < 4; ni++) {
        const int c = bn + warp_n0 + ni * 8 + (lane & 3) * 2;
        const float bb0 = bias[c], bb1 = bias[c + 1];
        float p0 = 0.f, p1 = 0.f;
        if (MODE == 1) { p0 = extra[c]; p1 = extra[c + 1]; }
#pragma unroll
        for (int mi = 0; mi < 4; mi++) {
            const int r0 = bm + warp_m0 + mi * 16 + (lane >> 2);
#pragma unroll
            for (int half = 0; half < 2; half++) {
                const int row = r0 + half * 8;
                float v0 = acc[mi][ni][half * 2 + 0] + bb0;
                float v1 = acc[mi][ni][half * 2 + 1] + bb1;
                if (MODE == 1) { v0 = tanhf(v0) * p0; v1 = tanhf(v1) * p1; }
                if (MODE == 2) {
                    const float2 rr = *(const float2*)(extra + (size_t)row * DD + c);
                    v0 += rr.x; v1 += rr.y;
                }
                *(float2*)(C + (size_t)row * DD + c) = make_float2(v0, v1);
            }
        }
    }
}

// ------------- fused bind + intra-chunk cumsum + retrieve + layernorm ----------
__global__ void __launch_bounds__(1024)
scan_ln(const float* __restrict__ val, const float* __restrict__ kp,
        const float* __restrict__ qp, const float* __restrict__ lng,
        const float* __restrict__ lnb, float* __restrict__ outp)
{
    __shared__ float rs[32], rs2[32];
    __shared__ float s_mu, s_rstd;

    const int d    = threadIdx.x;
    const int lane = d & 31;
    const int wid  = d >> 5;
    const size_t base = (size_t)blockIdx.x * CHUNK * DD + d;
    const float gd = lng[d], bd = lnb[d];

    float ar = 0.f, ai = 0.f;
    for (int r = 0; r < CHUNK; r++) {
        const size_t idx = base + (size_t)r * DD;
        const float v  = val[idx];
        const float pk = kp[idx];
        const float pq = qp[idx];
        float sk, ck, sq, cq;
        sincosf(pk, &sk, &ck);
        sincosf(pq, &sq, &cq);
        ar = fmaf(v, ck, ar);
        ai = fmaf(v, sk, ai);
        const float x = (ar * cq + ai * sq) * 0.03125f;

        float s = x, s2 = x * x;
#pragma unroll
        for (int o = 16; o; o >>= 1) {
            s  += __shfl_xor_sync(0xffffffffu, s,  o);
            s2 += __shfl_xor_sync(0xffffffffu, s2, o);
        }
        if (lane == 0) { rs[wid] = s; rs2[wid] = s2; }
        __syncthreads();
        if (wid == 0) {
            s  = rs[lane];
            s2 = rs2[lane];
#pragma unroll
            for (int o = 16; o; o >>= 1) {
                s  += __shfl_xor_sync(0xffffffffu, s,  o);
                s2 += __shfl_xor_sync(0xffffffffu, s2, o);
            }
            if (lane == 0) {
                const float mu  = s * (1.f / DD);
                const float var = s2 * (1.f / DD) - mu * mu;
                s_mu   = mu;
                s_rstd = rsqrtf(var + 1e-5f);
            }
        }
        __syncthreads();
        outp[idx] = (x - s_mu) * s_rstd * gd + bd;
    }
}

// --------------------------------- launch --------------------------------------
extern "C" void kernel_launch(void* const* d_in, const int* in_sizes, int n_in,
                              void* d_out, int out_size)
{
    const float* x   = (const float*)d_in[0];
    const float* Wk  = (const float*)d_in[1];
    const float* bk  = (const float*)d_in[2];
    const float* Wv  = (const float*)d_in[3];
    const float* bv  = (const float*)d_in[4];
    const float* Wq  = (const float*)d_in[5];
    const float* bq  = (const float*)d_in[6];
    const float* Wkp = (const float*)d_in[7];
    const float* bkp = (const float*)d_in[8];
    const float* Wqp = (const float*)d_in[9];
    const float* bqp = (const float*)d_in[10];
    const float* ps  = (const float*)d_in[11];
    const float* lng = (const float*)d_in[12];
    const float* lnb = (const float*)d_in[13];
    const float* Wo  = (const float*)d_in[14];
    const float* bo  = (const float*)d_in[15];
    float* out = (float*)d_out;

    float *pkey, *pval, *pqry, *pkp, *pqp, *pln;
    cudaGetSymbolAddress((void**)&pkey, g_key);
    cudaGetSymbolAddress((void**)&pval, g_val);
    cudaGetSymbolAddress((void**)&pqry, g_qry);
    cudaGetSymbolAddress((void**)&pkp,  g_kp);
    cudaGetSymbolAddress((void**)&pqp,  g_qp);
    cudaGetSymbolAddress((void**)&pln,  g_ln);

    cudaFuncSetAttribute(gemm_mma<0>, cudaFuncAttributeMaxDynamicSharedMemorySize, SMEM_BYTES);
    cudaFuncSetAttribute(gemm_mma<1>, cudaFuncAttributeMaxDynamicSharedMemorySize, SMEM_BYTES);
    cudaFuncSetAttribute(gemm_mma<2>, cudaFuncAttributeMaxDynamicSharedMemorySize, SMEM_BYTES);

    dim3 blk(256);
    // K/V/Q projections fused (z selects weights)
    gemm_mma<0><<<dim3(8, 128, 3), blk, SMEM_BYTES>>>(
        x, x, x, Wk, Wv, Wq, bk, bv, bq, nullptr, pkey, pval, pqry);
    // phase projections fused (tanh * phase_scale epilogue)
    gemm_mma<1><<<dim3(8, 128, 2), blk, SMEM_BYTES>>>(
        pkey, pqry, pqry, Wkp, Wqp, Wqp, bkp, bqp, bqp, ps, pkp, pqp, pqp);
    // bind + chunked cumsum + retrieve + layernorm
    scan_ln<<<MB / CHUNK, 1024>>>(pval, pkp, pqp, lng, lnb, pln);
    // output projection + residual
    gemm_mma<2><<<dim3(8, 128, 1), blk, SMEM_BYTES>>>(
        pln, pln, pln, Wo, Wo, Wo, bo, bo, bo, x, out, out, out);
}

// round 4
// speedup vs baseline: 2.6829x; 1.0992x over previous
#include <cuda_runtime.h>
#include <cuda_fp16.h>
#include <math.h>
#include <stdint.h>

#define DD    1024
#define MB    16384
#define CHUNK 64
#define BM    256
#define BN    128
#define BK    64
#define NKC   (DD / BK)        // 16
#define STAGE_B 98304u         // Ah 32K | Al 32K | Wh 16K | Wl 16K
#define SMEM_BYTES (2u * STAGE_B)

// ---------------- scratch (static device arrays; no allocation) ----------------
__device__ __half g_xh[MB * DD], g_xl[MB * DD];
__device__ __half g_kh[MB * DD], g_kl[MB * DD];
__device__ __half g_qh[MB * DD], g_ql[MB * DD];
__device__ __half g_lnh[MB * DD], g_lnl[MB * DD];
__device__ float  g_val[MB * DD];
__device__ float  g_kp [MB * DD], g_qp[MB * DD];
__device__ __half g_wh[6][DD * DD], g_wl[6][DD * DD];

// ---------------- helpers ----------------
__device__ __forceinline__ uint32_t smem_u32(const void* p) {
    uint32_t a;
    asm("{ .reg .u64 t; cvta.to.shared.u64 t, %1; cvt.u32.u64 %0, t; }" : "=r"(a) : "l"(p));
    return a;
}
__device__ __forceinline__ void cp_async16(uint32_t dst, const void* src) {
    asm volatile("cp.async.cg.shared.global [%0], [%1], 16;" :: "r"(dst), "l"(src));
}
__device__ __forceinline__ void cp_commit() {
    asm volatile("cp.async.commit_group;" ::: "memory");
}
template<int N>
__device__ __forceinline__ void cp_wait() {
    asm volatile("cp.async.wait_group %0;" :: "n"(N) : "memory");
}
__device__ __forceinline__ void ldsm4(uint32_t* r, uint32_t addr) {
    asm volatile("ldmatrix.sync.aligned.m8n8.x4.shared.b16 {%0,%1,%2,%3}, [%4];"
                 : "=r"(r[0]), "=r"(r[1]), "=r"(r[2]), "=r"(r[3]) : "r"(addr));
}
__device__ __forceinline__ void mma16816(float* c, const uint32_t* a, uint32_t b0, uint32_t b1) {
    asm volatile(
        "mma.sync.aligned.m16n8k16.row.col.f32.f16.f16.f32 "
        "{%0,%1,%2,%3}, {%4,%5,%6,%7}, {%8,%9}, {%0,%1,%2,%3};"
        : "+f"(c[0]), "+f"(c[1]), "+f"(c[2]), "+f"(c[3])
        : "r"(a[0]), "r"(a[1]), "r"(a[2]), "r"(a[3]), "r"(b0), "r"(b1));
}
__device__ __forceinline__ void split2(float v0, float v1, uint32_t& h, uint32_t& l) {
    __half2 hh = __floats2half2_rn(v0, v1);
    float2 f = __half22float2(hh);
    __half2 ll = __floats2half2_rn(v0 - f.x, v1 - f.y);
    h = *(uint32_t*)&hh; l = *(uint32_t*)&ll;
}

// ---------------- fp32 -> (hi fp16, lo fp16) split, 3 matrices per launch ------
__global__ void __launch_bounds__(256)
split3(const float* __restrict__ s0, const float* __restrict__ s1, const float* __restrict__ s2,
       __half* h0, __half* l0, __half* h1, __half* l1, __half* h2, __half* l2)
{
    const int z = blockIdx.y;
    const float* s = (z == 0) ? s0 : (z == 1) ? s1 : s2;
    __half* h = (z == 0) ? h0 : (z == 1) ? h1 : h2;
    __half* l = (z == 0) ? l0 : (z == 1) ? l1 : l2;
    const size_t i = ((size_t)blockIdx.x * 256 + threadIdx.x) * 4;
    const float4 v = *(const float4*)(s + i);
    uint32_t ha, la, hb, lb;
    split2(v.x, v.y, ha, la);
    split2(v.z, v.w, hb, lb);
    *(uint2*)(h + i) = make_uint2(ha, hb);
    *(uint2*)(l + i) = make_uint2(la, lb);
}

// ---------------- GEMM args ----------------
struct GemmArgs {
    const __half* Ah[3]; const __half* Al[3];
    const __half* Wh[3]; const __half* Wl[3];
    const float*  bias[3];
    const float*  extra;            // MODE1: phase_scale ; MODE2: residual x
    float*  Cf [3];                 // fp32 output (or null)
    __half* Ch [3]; __half* Cl[3];  // split fp16 output (or null)
};

// ---------------- mma.sync GEMM: C[256,128] tile = A @ W^T (NPASS Karatsuba) ---
// MODE 0: v = acc + bias
// MODE 1: v = tanh(acc + bias) * extra[n]
// MODE 2: v = acc + bias + extra[row, n]
template<int MODE, int NPASS>
__global__ void __launch_bounds__(256, 1)
gemm_mma(GemmArgs ga)
{
    extern __shared__ char smem[];
    const int tid = threadIdx.x;
    const int z = blockIdx.z;
    const __half* Ahg = ga.Ah[z];
    const __half* Alg = ga.Al[z];
    const __half* Whg = ga.Wh[z];
    const __half* Wlg = ga.Wl[z];
    const float*  bias = ga.bias[z];

    const int bm = blockIdx.y * BM;
    const int bn = blockIdx.x * BN;
    const uint32_t sbu = smem_u32(smem);

    // ---- cp.async stage loader ----
    auto issue = [&](int kt, int s) {
        const uint32_t st = sbu + (uint32_t)s * STAGE_B;
        const int kof = kt * BK;
#pragma unroll
        for (int i = 0; i < 8; i++) {
            const int idx = tid + (i << 8);
            const int row = idx >> 3, c = idx & 7;
            const uint32_t so = st + (uint32_t)row * 128u
                              + (((uint32_t)c * 16u) ^ (((uint32_t)row & 7u) << 4));
            const size_t g = (size_t)(bm + row) * DD + kof + c * 8;
            cp_async16(so,           Ahg + g);
            cp_async16(so + 32768u,  Alg + g);
        }
#pragma unroll
        for (int i = 0; i < 4; i++) {
            const int idx = tid + (i << 8);
            const int row = idx >> 3, c = idx & 7;
            const uint32_t so = st + 65536u + (uint32_t)row * 128u
                              + (((uint32_t)c * 16u) ^ (((uint32_t)row & 7u) << 4));
            const size_t g = (size_t)(bn + row) * DD + kof + c * 8;
            cp_async16(so, Whg + g);
            if (NPASS == 3) cp_async16(so + 16384u, Wlg + g);
        }
    };

    // ---- warp compute mapping: 8 warps 4x2, warp tile 64x64 ----
    const int warp = tid >> 5, lane = tid & 31;
    const int wm0 = (warp >> 1) * 64;
    const int wn0 = (warp & 1) * 64;
    const int lr = lane & 15;
    const uint32_t lc   = ((uint32_t)lane >> 4) * 16u;
    const uint32_t xorv = ((uint32_t)lane & 7u) << 4;

    float acc[4][8][4];
#pragma unroll
    for (int mi = 0; mi < 4; mi++)
#pragma unroll
        for (int ni = 0; ni < 8; ni++)
#pragma unroll
            for (int q = 0; q < 4; q++) acc[mi][ni][q] = 0.f;

    auto compute = [&](int s) {
        const uint32_t sA = sbu + (uint32_t)s * STAGE_B;
        const uint32_t sW = sA + 65536u;
#pragma unroll
        for (int kk = 0; kk < 4; kk++) {
            const uint32_t koff = (((uint32_t)kk * 32u) + lc) ^ xorv;
            uint32_t ah[4][4], al[4][4], wh[4][4], wl[4][4];
#pragma unroll
            for (int mi = 0; mi < 4; mi++) {
                const uint32_t rb = (uint32_t)((wm0 + mi * 16 + lr) * 128) + koff;
                ldsm4(ah[mi], sA + rb);
                ldsm4(al[mi], sA + 32768u + rb);
            }
#pragma unroll
            for (int g = 0; g < 4; g++) {
                const uint32_t rb = (uint32_t)((wn0 + g * 16 + lr) * 128) + koff;
                ldsm4(wh[g], sW + rb);
                if (NPASS == 3) ldsm4(wl[g], sW + 16384u + rb);
            }
#pragma unroll
            for (int mi = 0; mi < 4; mi++)
#pragma unroll
                for (int ni = 0; ni < 8; ni++) {
                    const uint32_t* b = wh[ni >> 1];
                    mma16816(acc[mi][ni], ah[mi], b[ni & 1], b[(ni & 1) + 2]);
                }
#pragma unroll
            for (int mi = 0; mi < 4; mi++)
#pragma unroll
                for (int ni = 0; ni < 8; ni++) {
                    const uint32_t* b = wh[ni >> 1];
                    mma16816(acc[mi][ni], al[mi], b[ni & 1], b[(ni & 1) + 2]);
                }
            if (NPASS == 3) {
#pragma unroll
                for (int mi = 0; mi < 4; mi++)
#pragma unroll
                    for (int ni = 0; ni < 8; ni++) {
                        const uint32_t* b = wl[ni >> 1];
                        mma16816(acc[mi][ni], ah[mi], b[ni & 1], b[(ni & 1) + 2]);
                    }
            }
        }
    };

    // ---- pipeline ----
    issue(0, 0); cp_commit();
    issue(1, 1); cp_commit();
    cp_wait<1>();
    __syncthreads();
#pragma unroll 1
    for (int kt = 0; kt < NKC; kt++) {
        compute(kt & 1);
        __syncthreads();
        if (kt + 2 < NKC) issue(kt + 2, kt & 1);
        cp_commit();
        cp_wait<1>();
        __syncthreads();
    }

    // ---- epilogue ----
    const float* extra = ga.extra;
    float*  Cf = ga.Cf[z];
    __half* Ch = ga.Ch[z];
    __half* Cl = ga.Cl[z];

#pragma unroll
    for (int ni = 0; ni < 8; ni++) {
        const int c = bn + wn0 + ni * 8 + (lane & 3) * 2;
        const float b0 = bias[c], b1 = bias[c + 1];
        float p0 = 0.f, p1 = 0.f;
        if (MODE == 1) { p0 = extra[c]; p1 = extra[c + 1]; }
#pragma unroll
        for (int mi = 0; mi < 4; mi++) {
#pragma unroll
            for (int hf = 0; hf < 2; hf++) {
                const int row = bm + wm0 + mi * 16 + (lane >> 2) + hf * 8;
                float v0 = acc[mi][ni][hf * 2 + 0] + b0;
                float v1 = acc[mi][ni][hf * 2 + 1] + b1;
                if (MODE == 1) { v0 = tanhf(v0) * p0; v1 = tanhf(v1) * p1; }
                if (MODE == 2) {
                    const float2 rr = *(const float2*)(extra + (size_t)row * DD + c);
                    v0 += rr.x; v1 += rr.y;
                }
                if (Cf) *(float2*)(Cf + (size_t)row * DD + c) = make_float2(v0, v1);
                if (Ch) {
                    uint32_t h, l;
                    split2(v0, v1, h, l);
                    *(uint32_t*)(Ch + (size_t)row * DD + c) = h;
                    *(uint32_t*)(Cl + (size_t)row * DD + c) = l;
                }
            }
        }
    }
}

// ------------- fused bind + intra-chunk cumsum + retrieve + layernorm ----------
// writes split fp16 (consumed by the output GEMM)
__global__ void __launch_bounds__(1024)
scan_ln(const float* __restrict__ val, const float* __restrict__ kp,
        const float* __restrict__ qp, const float* __restrict__ lng,
        const float* __restrict__ lnb, __half* __restrict__ oh, __half* __restrict__ ol)
{
    __shared__ float rs[32], rs2[32];
    __shared__ float s_mu, s_rstd;

    const int d    = threadIdx.x;
    const int lane = d & 31;
    const int wid  = d >> 5;
    const size_t base = (size_t)blockIdx.x * CHUNK * DD + d;
    const float gd = lng[d], bd = lnb[d];

    float ar = 0.f, ai = 0.f;
    for (int r = 0; r < CHUNK; r++) {
        const size_t idx = base + (size_t)r * DD;
        const float v  = val[idx];
        const float pk = kp[idx];
        const float pq = qp[idx];
        float sk, ck, sq, cq;
        sincosf(pk, &sk, &ck);
        sincosf(pq, &sq, &cq);
        ar = fmaf(v, ck, ar);
        ai = fmaf(v, sk, ai);
        const float x = (ar * cq + ai * sq) * 0.03125f;

        float s = x, s2 = x * x;
#pragma unroll
        for (int o = 16; o; o >>= 1) {
            s  += __shfl_xor_sync(0xffffffffu, s,  o);
            s2 += __shfl_xor_sync(0xffffffffu, s2, o);
        }
        if (lane == 0) { rs[wid] = s; rs2[wid] = s2; }
        __syncthreads();
        if (wid == 0) {
            s  = rs[lane];
            s2 = rs2[lane];
#pragma unroll
            for (int o = 16; o; o >>= 1) {
                s  += __shfl_xor_sync(0xffffffffu, s,  o);
                s2 += __shfl_xor_sync(0xffffffffu, s2, o);
            }
            if (lane == 0) {
                const float mu  = s * (1.f / DD);
                const float var = s2 * (1.f / DD) - mu * mu;
                s_mu   = mu;
                s_rstd = rsqrtf(var + 1e-5f);
            }
        }
        __syncthreads();
        const float y = (x - s_mu) * s_rstd * gd + bd;
        const __half h = __float2half_rn(y);
        oh[idx] = h;
        ol[idx] = __float2half_rn(y - __half2float(h));
    }
}

// --------------------------------- launch --------------------------------------
extern "C" void kernel_launch(void* const* d_in, const int* in_sizes, int n_in,
                              void* d_out, int out_size)
{
    const float* x   = (const float*)d_in[0];
    const float* Wk  = (const float*)d_in[1];
    const float* bk  = (const float*)d_in[2];
    const float* Wv  = (const float*)d_in[3];
    const float* bv  = (const float*)d_in[4];
    const float* Wq  = (const float*)d_in[5];
    const float* bq  = (const float*)d_in[6];
    const float* Wkp = (const float*)d_in[7];
    const float* bkp = (const float*)d_in[8];
    const float* Wqp = (const float*)d_in[9];
    const float* bqp = (const float*)d_in[10];
    const float* ps  = (const float*)d_in[11];
    const float* lng = (const float*)d_in[12];
    const float* lnb = (const float*)d_in[13];
    const float* Wo  = (const float*)d_in[14];
    const float* bo  = (const float*)d_in[15];
    float* out = (float*)d_out;

    __half *xh, *xl, *kh, *kl, *qh, *ql, *lnh, *lnl;
    float *val, *kpv, *qpv;
    __half (*wh)[DD * DD], (*wl)[DD * DD];
    cudaGetSymbolAddress((void**)&xh,  g_xh);
    cudaGetSymbolAddress((void**)&xl,  g_xl);
    cudaGetSymbolAddress((void**)&kh,  g_kh);
    cudaGetSymbolAddress((void**)&kl,  g_kl);
    cudaGetSymbolAddress((void**)&qh,  g_qh);
    cudaGetSymbolAddress((void**)&ql,  g_ql);
    cudaGetSymbolAddress((void**)&lnh, g_lnh);
    cudaGetSymbolAddress((void**)&lnl, g_lnl);
    cudaGetSymbolAddress((void**)&val, g_val);
    cudaGetSymbolAddress((void**)&kpv, g_kp);
    cudaGetSymbolAddress((void**)&qpv, g_qp);
    cudaGetSymbolAddress((void**)&wh,  g_wh);
    cudaGetSymbolAddress((void**)&wl,  g_wl);

    cudaFuncSetAttribute(gemm_mma<0,3>, cudaFuncAttributeMaxDynamicSharedMemorySize, SMEM_BYTES);
    cudaFuncSetAttribute(gemm_mma<1,3>, cudaFuncAttributeMaxDynamicSharedMemorySize, SMEM_BYTES);
    cudaFuncSetAttribute(gemm_mma<2,2>, cudaFuncAttributeMaxDynamicSharedMemorySize, SMEM_BYTES);

    // splits: weights (0:Wk 1:Wv 2:Wq 3:Wkp 4:Wqp 5:Wo) and x
    split3<<<dim3(DD * DD / 1024, 3), 256>>>(Wk, Wv, Wq,
        wh[0], wl[0], wh[1], wl[1], wh[2], wl[2]);
    split3<<<dim3(DD * DD / 1024, 3), 256>>>(Wkp, Wqp, Wo,
        wh[3], wl[3], wh[4], wl[4], wh[5], wl[5]);
    split3<<<dim3(MB * DD / 1024, 1), 256>>>(x, x, x, xh, xl, xh, xl, xh, xl);

    dim3 blk(256);

    // K/V/Q projections: key,qry -> split fp16 ; val -> fp32
    {
        GemmArgs a = {};
        a.Ah[0] = a.Ah[1] = a.Ah[2] = xh;
        a.Al[0] = a.Al[1] = a.Al[2] = xl;
        a.Wh[0] = wh[0]; a.Wl[0] = wl[0]; a.bias[0] = bk;
        a.Wh[1] = wh[1]; a.Wl[1] = wl[1]; a.bias[1] = bv;
        a.Wh[2] = wh[2]; a.Wl[2] = wl[2]; a.bias[2] = bq;
        a.Ch[0] = kh; a.Cl[0] = kl;
        a.Cf[1] = val;
        a.Ch[2] = qh; a.Cl[2] = ql;
        gemm_mma<0,3><<<dim3(DD / BN, MB / BM, 3), blk, SMEM_BYTES>>>(a);
    }
    // phase projections: kp, qp fp32 (tanh * phase_scale epilogue)
    {
        GemmArgs a = {};
        a.Ah[0] = kh; a.Al[0] = kl; a.Wh[0] = wh[3]; a.Wl[0] = wl[3]; a.bias[0] = bkp;
        a.Ah[1] = qh; a.Al[1] = ql; a.Wh[1] = wh[4]; a.Wl[1] = wl[4]; a.bias[1] = bqp;
        a.extra = ps;
        a.Cf[0] = kpv; a.Cf[1] = qpv;
        gemm_mma<1,3><<<dim3(DD / BN, MB / BM, 2), blk, SMEM_BYTES>>>(a);
    }
    // bind + chunked cumsum + retrieve + layernorm -> split fp16
    scan_ln<<<MB / CHUNK, 1024>>>(val, kpv, qpv, lng, lnb, lnh, lnl);
    // output projection (2-pass) + residual
    {
        GemmArgs a = {};
        a.Ah[0] = lnh; a.Al[0] = lnl; a.Wh[0] = wh[5]; a.Wl[0] = wl[5]; a.bias[0] = bo;
        a.extra = x;
        a.Cf[0] = out;
        gemm_mma<2,2><<<dim3(DD / BN, MB / BM, 1), blk, SMEM_BYTES>>>(a);
    }
}

// round 5
// speedup vs baseline: 3.4682x; 1.2927x over previous
#include <cuda_runtime.h>
#include <cuda_fp16.h>
#include <math.h>
#include <stdint.h>

#define DD    1024
#define MB    16384
#define CHUNK 64
#define BM    256
#define BN    128
#define BK    64
#define NKC   (DD / BK)        // 16
#define STAGE_B 81920u         // Ah 32K | Al 32K | Wh 16K
#define SMEM_BYTES (2u * STAGE_B)

// ---------------- scratch (static device arrays; no allocation) ----------------
__device__ __half g_xh[MB * DD], g_xl[MB * DD];
__device__ __half g_kh[MB * DD], g_kl[MB * DD];
__device__ __half g_qh[MB * DD], g_ql[MB * DD];
__device__ __half g_lnh[MB * DD], g_lnl[MB * DD];
__device__ float  g_val[MB * DD];
__device__ float  g_kp [MB * DD], g_qp[MB * DD];
__device__ __half g_wh[6][DD * DD];

// ---------------- helpers ----------------
__device__ __forceinline__ uint32_t smem_u32(const void* p) {
    uint32_t a;
    asm("{ .reg .u64 t; cvta.to.shared.u64 t, %1; cvt.u32.u64 %0, t; }" : "=r"(a) : "l"(p));
    return a;
}
__device__ __forceinline__ void cp_async16(uint32_t dst, const void* src) {
    asm volatile("cp.async.cg.shared.global [%0], [%1], 16;" :: "r"(dst), "l"(src));
}
__device__ __forceinline__ void cp_commit() {
    asm volatile("cp.async.commit_group;" ::: "memory");
}
template<int N>
__device__ __forceinline__ void cp_wait() {
    asm volatile("cp.async.wait_group %0;" :: "n"(N) : "memory");
}
__device__ __forceinline__ void ldsm4(uint32_t* r, uint32_t addr) {
    asm volatile("ldmatrix.sync.aligned.m8n8.x4.shared.b16 {%0,%1,%2,%3}, [%4];"
                 : "=r"(r[0]), "=r"(r[1]), "=r"(r[2]), "=r"(r[3]) : "r"(addr));
}
__device__ __forceinline__ void mma16816(float* c, const uint32_t* a, uint32_t b0, uint32_t b1) {
    asm volatile(
        "mma.sync.aligned.m16n8k16.row.col.f32.f16.f16.f32 "
        "{%0,%1,%2,%3}, {%4,%5,%6,%7}, {%8,%9}, {%0,%1,%2,%3};"
        : "+f"(c[0]), "+f"(c[1]), "+f"(c[2]), "+f"(c[3])
        : "r"(a[0]), "r"(a[1]), "r"(a[2]), "r"(a[3]), "r"(b0), "r"(b1));
}
__device__ __forceinline__ void split2(float v0, float v1, uint32_t& h, uint32_t& l) {
    __half2 hh = __floats2half2_rn(v0, v1);
    float2 f = __half22float2(hh);
    __half2 ll = __floats2half2_rn(v0 - f.x, v1 - f.y);
    h = *(uint32_t*)&hh; l = *(uint32_t*)&ll;
}

// ---------------- fp32 -> (hi fp16 [, lo fp16]) split, 3 matrices per launch ---
__global__ void __launch_bounds__(256)
split3(const float* __restrict__ s0, const float* __restrict__ s1, const float* __restrict__ s2,
       __half* h0, __half* l0, __half* h1, __half* l1, __half* h2, __half* l2)
{
    const int z = blockIdx.y;
    const float* s = (z == 0) ? s0 : (z == 1) ? s1 : s2;
    __half* h = (z == 0) ? h0 : (z == 1) ? h1 : h2;
    __half* l = (z == 0) ? l0 : (z == 1) ? l1 : l2;
    const size_t i = ((size_t)blockIdx.x * 256 + threadIdx.x) * 4;
    const float4 v = *(const float4*)(s + i);
    uint32_t ha, la, hb, lb;
    split2(v.x, v.y, ha, la);
    split2(v.z, v.w, hb, lb);
    *(uint2*)(h + i) = make_uint2(ha, hb);
    if (l) *(uint2*)(l + i) = make_uint2(la, lb);
}

// ---------------- GEMM args ----------------
struct GemmArgs {
    const __half* Ah[3]; const __half* Al[3];
    const __half* Wh[3];
    const float*  bias[3];
    const float*  extra;            // MODE1: phase_scale ; MODE2: residual x
    float*  Cf [3];                 // fp32 output (or null)
    __half* Ch [3]; __half* Cl[3];  // split fp16 output (or null)
};

// ------- mma.sync GEMM: C[256,128] tile = (Ah+Al) @ Wh^T (2-pass Karatsuba) ----
// MODE 0: v = acc + bias
// MODE 1: v = tanh(acc + bias) * extra[n]
// MODE 2: v = acc + bias + extra[row, n]
template<int MODE>
__global__ void __launch_bounds__(256, 1)
gemm_mma(GemmArgs ga)
{
    extern __shared__ char smem[];
    const int tid = threadIdx.x;
    const int z = blockIdx.z;
    const __half* Ahg = ga.Ah[z];
    const __half* Alg = ga.Al[z];
    const __half* Whg = ga.Wh[z];
    const float*  bias = ga.bias[z];

    const int bm = blockIdx.y * BM;
    const int bn = blockIdx.x * BN;
    const uint32_t sbu = smem_u32(smem);

    // ---- cp.async stage loader: Ah(32K) Al(32K) Wh(16K) ----
    auto issue = [&](int kt, int s) {
        const uint32_t st = sbu + (uint32_t)s * STAGE_B;
        const int kof = kt * BK;
#pragma unroll
        for (int i = 0; i < 8; i++) {
            const int idx = tid + (i << 8);
            const int row = idx >> 3, c = idx & 7;
            const uint32_t so = st + (uint32_t)row * 128u
                              + (((uint32_t)c * 16u) ^ (((uint32_t)row & 7u) << 4));
            const size_t g = (size_t)(bm + row) * DD + kof + c * 8;
            cp_async16(so,          Ahg + g);
            cp_async16(so + 32768u, Alg + g);
        }
#pragma unroll
        for (int i = 0; i < 4; i++) {
            const int idx = tid + (i << 8);
            const int row = idx >> 3, c = idx & 7;
            const uint32_t so = st + 65536u + (uint32_t)row * 128u
                              + (((uint32_t)c * 16u) ^ (((uint32_t)row & 7u) << 4));
            cp_async16(so, Whg + (size_t)(bn + row) * DD + kof + c * 8);
        }
    };

    // ---- warp compute mapping: 8 warps 4x2, warp tile 64x64 ----
    const int warp = tid >> 5, lane = tid & 31;
    const int wm0 = (warp >> 1) * 64;
    const int wn0 = (warp & 1) * 64;
    const int lr = lane & 15;
    const uint32_t lc   = ((uint32_t)lane >> 4) * 16u;
    const uint32_t xorv = ((uint32_t)lane & 7u) << 4;

    float acc[4][8][4];
#pragma unroll
    for (int mi = 0; mi < 4; mi++)
#pragma unroll
        for (int ni = 0; ni < 8; ni++)
#pragma unroll
            for (int q = 0; q < 4; q++) acc[mi][ni][q] = 0.f;

    auto compute = [&](int s) {
        const uint32_t sA = sbu + (uint32_t)s * STAGE_B;
        const uint32_t sW = sA + 65536u;
#pragma unroll
        for (int kk = 0; kk < 4; kk++) {
            const uint32_t koff = (((uint32_t)kk * 32u) + lc) ^ xorv;
            uint32_t ah[4][4], al[4][4], wh[4][4];
#pragma unroll
            for (int mi = 0; mi < 4; mi++) {
                const uint32_t rb = (uint32_t)((wm0 + mi * 16 + lr) * 128) + koff;
                ldsm4(ah[mi], sA + rb);
                ldsm4(al[mi], sA + 32768u + rb);
            }
#pragma unroll
            for (int g = 0; g < 4; g++)
                ldsm4(wh[g], sW + (uint32_t)((wn0 + g * 16 + lr) * 128) + koff);
#pragma unroll
            for (int mi = 0; mi < 4; mi++)
#pragma unroll
                for (int ni = 0; ni < 8; ni++) {
                    const uint32_t* b = wh[ni >> 1];
                    mma16816(acc[mi][ni], ah[mi], b[ni & 1], b[(ni & 1) + 2]);
                }
#pragma unroll
            for (int mi = 0; mi < 4; mi++)
#pragma unroll
                for (int ni = 0; ni < 8; ni++) {
                    const uint32_t* b = wh[ni >> 1];
                    mma16816(acc[mi][ni], al[mi], b[ni & 1], b[(ni & 1) + 2]);
                }
        }
    };

    // ---- pipeline ----
    issue(0, 0); cp_commit();
    issue(1, 1); cp_commit();
    cp_wait<1>();
    __syncthreads();
#pragma unroll 1
    for (int kt = 0; kt < NKC; kt++) {
        compute(kt & 1);
        __syncthreads();
        if (kt + 2 < NKC) issue(kt + 2, kt & 1);
        cp_commit();
        cp_wait<1>();
        __syncthreads();
    }

    // ---- epilogue ----
    const float* extra = ga.extra;
    float*  Cf = ga.Cf[z];
    __half* Ch = ga.Ch[z];
    __half* Cl = ga.Cl[z];

#pragma unroll
    for (int ni = 0; ni < 8; ni++) {
        const int c = bn + wn0 + ni * 8 + (lane & 3) * 2;
        const float b0 = bias[c], b1 = bias[c + 1];
        float p0 = 0.f, p1 = 0.f;
        if (MODE == 1) { p0 = extra[c]; p1 = extra[c + 1]; }
#pragma unroll
        for (int mi = 0; mi < 4; mi++) {
#pragma unroll
            for (int hf = 0; hf < 2; hf++) {
                const int row = bm + wm0 + mi * 16 + (lane >> 2) + hf * 8;
                float v0 = acc[mi][ni][hf * 2 + 0] + b0;
                float v1 = acc[mi][ni][hf * 2 + 1] + b1;
                if (MODE == 1) { v0 = tanhf(v0) * p0; v1 = tanhf(v1) * p1; }
                if (MODE == 2) {
                    const float2 rr = *(const float2*)(extra + (size_t)row * DD + c);
                    v0 += rr.x; v1 += rr.y;
                }
                if (Cf) *(float2*)(Cf + (size_t)row * DD + c) = make_float2(v0, v1);
                if (Ch) {
                    uint32_t h, l;
                    split2(v0, v1, h, l);
                    *(uint32_t*)(Ch + (size_t)row * DD + c) = h;
                    *(uint32_t*)(Cl + (size_t)row * DD + c) = l;
                }
            }
        }
    }
}

// ------------- fused bind + intra-chunk cumsum + retrieve + layernorm ----------
__global__ void __launch_bounds__(1024)
scan_ln(const float* __restrict__ val, const float* __restrict__ kp,
        const float* __restrict__ qp, const float* __restrict__ lng,
        const float* __restrict__ lnb, __half* __restrict__ oh, __half* __restrict__ ol)
{
    __shared__ float rs[32], rs2[32];
    __shared__ float s_mu, s_rstd;

    const int d    = threadIdx.x;
    const int lane = d & 31;
    const int wid  = d >> 5;
    const size_t base = (size_t)blockIdx.x * CHUNK * DD + d;
    const float gd = lng[d], bd = lnb[d];

    float ar = 0.f, ai = 0.f;
    for (int r = 0; r < CHUNK; r++) {
        const size_t idx = base + (size_t)r * DD;
        const float v  = val[idx];
        const float pk = kp[idx];
        const float pq = qp[idx];
        float sk, ck, sq, cq;
        sincosf(pk, &sk, &ck);
        sincosf(pq, &sq, &cq);
        ar = fmaf(v, ck, ar);
        ai = fmaf(v, sk, ai);
        const float x = (ar * cq + ai * sq) * 0.03125f;

        float s = x, s2 = x * x;
#pragma unroll
        for (int o = 16; o; o >>= 1) {
            s  += __shfl_xor_sync(0xffffffffu, s,  o);
            s2 += __shfl_xor_sync(0xffffffffu, s2, o);
        }
        if (lane == 0) { rs[wid] = s; rs2[wid] = s2; }
        __syncthreads();
        if (wid == 0) {
            s  = rs[lane];
            s2 = rs2[lane];
#pragma unroll
            for (int o = 16; o; o >>= 1) {
                s  += __shfl_xor_sync(0xffffffffu, s,  o);
                s2 += __shfl_xor_sync(0xffffffffu, s2, o);
            }
            if (lane == 0) {
                const float mu  = s * (1.f / DD);
                const float var = s2 * (1.f / DD) - mu * mu;
                s_mu   = mu;
                s_rstd = rsqrtf(var + 1e-5f);
            }
        }
        __syncthreads();
        const float y = (x - s_mu) * s_rstd * gd + bd;
        const __half h = __float2half_rn(y);
        oh[idx] = h;
        ol[idx] = __float2half_rn(y - __half2float(h));
    }
}

// --------------------------------- launch --------------------------------------
extern "C" void kernel_launch(void* const* d_in, const int* in_sizes, int n_in,
                              void* d_out, int out_size)
{
    const float* x   = (const float*)d_in[0];
    const float* Wk  = (const float*)d_in[1];
    const float* bk  = (const float*)d_in[2];
    const float* Wv  = (const float*)d_in[3];
    const float* bv  = (const float*)d_in[4];
    const float* Wq  = (const float*)d_in[5];
    const float* bq  = (const float*)d_in[6];
    const float* Wkp = (const float*)d_in[7];
    const float* bkp = (const float*)d_in[8];
    const float* Wqp = (const float*)d_in[9];
    const float* bqp = (const float*)d_in[10];
    const float* ps  = (const float*)d_in[11];
    const float* lng = (const float*)d_in[12];
    const float* lnb = (const float*)d_in[13];
    const float* Wo  = (const float*)d_in[14];
    const float* bo  = (const float*)d_in[15];
    float* out = (float*)d_out;

    __half *xh, *xl, *kh, *kl, *qh, *ql, *lnh, *lnl;
    float *val, *kpv, *qpv;
    __half (*wh)[DD * DD];
    cudaGetSymbolAddress((void**)&xh,  g_xh);
    cudaGetSymbolAddress((void**)&xl,  g_xl);
    cudaGetSymbolAddress((void**)&kh,  g_kh);
    cudaGetSymbolAddress((void**)&kl,  g_kl);
    cudaGetSymbolAddress((void**)&qh,  g_qh);
    cudaGetSymbolAddress((void**)&ql,  g_ql);
    cudaGetSymbolAddress((void**)&lnh, g_lnh);
    cudaGetSymbolAddress((void**)&lnl, g_lnl);
    cudaGetSymbolAddress((void**)&val, g_val);
    cudaGetSymbolAddress((void**)&kpv, g_kp);
    cudaGetSymbolAddress((void**)&qpv, g_qp);
    cudaGetSymbolAddress((void**)&wh,  g_wh);

    cudaFuncSetAttribute(gemm_mma<0>, cudaFuncAttributeMaxDynamicSharedMemorySize, SMEM_BYTES);
    cudaFuncSetAttribute(gemm_mma<1>, cudaFuncAttributeMaxDynamicSharedMemorySize, SMEM_BYTES);
    cudaFuncSetAttribute(gemm_mma<2>, cudaFuncAttributeMaxDynamicSharedMemorySize, SMEM_BYTES);

    // weight splits: hi only (0:Wk 1:Wv 2:Wq 3:Wkp 4:Wqp 5:Wo); x: hi+lo
    split3<<<dim3(DD * DD / 1024, 3), 256>>>(Wk, Wv, Wq,
        wh[0], nullptr, wh[1], nullptr, wh[2], nullptr);
    split3<<<dim3(DD * DD / 1024, 3), 256>>>(Wkp, Wqp, Wo,
        wh[3], nullptr, wh[4], nullptr, wh[5], nullptr);
    split3<<<dim3(MB * DD / 1024, 1), 256>>>(x, x, x, xh, xl, xh, xl, xh, xl);

    dim3 blk(256);

    // K/V/Q projections: key,qry -> split fp16 ; val -> fp32
    {
        GemmArgs a = {};
        a.Ah[0] = a.Ah[1] = a.Ah[2] = xh;
        a.Al[0] = a.Al[1] = a.Al[2] = xl;
        a.Wh[0] = wh[0]; a.bias[0] = bk;
        a.Wh[1] = wh[1]; a.bias[1] = bv;
        a.Wh[2] = wh[2]; a.bias[2] = bq;
        a.Ch[0] = kh; a.Cl[0] = kl;
        a.Cf[1] = val;
        a.Ch[2] = qh; a.Cl[2] = ql;
        gemm_mma<0><<<dim3(DD / BN, MB / BM, 3), blk, SMEM_BYTES>>>(a);
    }
    // phase projections: kp, qp fp32 (tanh * phase_scale epilogue)
    {
        GemmArgs a = {};
        a.Ah[0] = kh; a.Al[0] = kl; a.Wh[0] = wh[3]; a.bias[0] = bkp;
        a.Ah[1] = qh; a.Al[1] = ql; a.Wh[1] = wh[4]; a.bias[1] = bqp;
        a.extra = ps;
        a.Cf[0] = kpv; a.Cf[1] = qpv;
        gemm_mma<1><<<dim3(DD / BN, MB / BM, 2), blk, SMEM_BYTES>>>(a);
    }
    // bind + chunked cumsum + retrieve + layernorm -> split fp16
    scan_ln<<<MB / CHUNK, 1024>>>(val, kpv, qpv, lng, lnb, lnh, lnl);
    // output projection + residual
    {
        GemmArgs a = {};
        a.Ah[0] = lnh; a.Al[0] = lnl; a.Wh[0] = wh[5]; a.bias[0] = bo;
        a.extra = x;
        a.Cf[0] = out;
        gemm_mma<2><<<dim3(DD / BN, MB / BM, 1), blk, SMEM_BYTES>>>(a);
    }
}

// round 6
// speedup vs baseline: 4.0109x; 1.1565x over previous
#include <cuda_runtime.h>
#include <cuda_fp16.h>
#include <math.h>
#include <stdint.h>

#define DD    1024
#define MB    16384
#define CHUNK 64
#define BM    128
#define BN    128
#define BK    64
#define NKC   (DD / BK)        // 16
#define STAGE_B 49152u         // Ah 16K | Al 16K | Wh 16K
#define SMEM_BYTES (2u * STAGE_B)

// ---------------- scratch (static device arrays; no allocation) ----------------
__device__ __half g_xh[MB * DD], g_xl[MB * DD];
__device__ __half g_kh[MB * DD], g_kl[MB * DD];
__device__ __half g_qh[MB * DD], g_ql[MB * DD];
__device__ __half g_lnh[MB * DD], g_lnl[MB * DD];
__device__ float  g_val[MB * DD];
__device__ float  g_kp [MB * DD], g_qp[MB * DD];
__device__ __half g_wh[6][DD * DD];

// ---------------- helpers ----------------
__device__ __forceinline__ uint32_t smem_u32(const void* p) {
    uint32_t a;
    asm("{ .reg .u64 t; cvta.to.shared.u64 t, %1; cvt.u32.u64 %0, t; }" : "=r"(a) : "l"(p));
    return a;
}
__device__ __forceinline__ void cp_async16(uint32_t dst, const void* src) {
    asm volatile("cp.async.cg.shared.global [%0], [%1], 16;" :: "r"(dst), "l"(src));
}
__device__ __forceinline__ void cp_commit() {
    asm volatile("cp.async.commit_group;" ::: "memory");
}
template<int N>
__device__ __forceinline__ void cp_wait() {
    asm volatile("cp.async.wait_group %0;" :: "n"(N) : "memory");
}
__device__ __forceinline__ void ldsm4(uint32_t* r, uint32_t addr) {
    asm volatile("ldmatrix.sync.aligned.m8n8.x4.shared.b16 {%0,%1,%2,%3}, [%4];"
                 : "=r"(r[0]), "=r"(r[1]), "=r"(r[2]), "=r"(r[3]) : "r"(addr));
}
__device__ __forceinline__ void mma16816(float* c, const uint32_t* a, uint32_t b0, uint32_t b1) {
    asm volatile(
        "mma.sync.aligned.m16n8k16.row.col.f32.f16.f16.f32 "
        "{%0,%1,%2,%3}, {%4,%5,%6,%7}, {%8,%9}, {%0,%1,%2,%3};"
        : "+f"(c[0]), "+f"(c[1]), "+f"(c[2]), "+f"(c[3])
        : "r"(a[0]), "r"(a[1]), "r"(a[2]), "r"(a[3]), "r"(b0), "r"(b1));
}
__device__ __forceinline__ void split2(float v0, float v1, uint32_t& h, uint32_t& l) {
    __half2 hh = __floats2half2_rn(v0, v1);
    float2 f = __half22float2(hh);
    __half2 ll = __floats2half2_rn(v0 - f.x, v1 - f.y);
    h = *(uint32_t*)&hh; l = *(uint32_t*)&ll;
}

// ---------------- fp32 -> (hi fp16 [, lo fp16]) split, 3 matrices per launch ---
__global__ void __launch_bounds__(256)
split3(const float* __restrict__ s0, const float* __restrict__ s1, const float* __restrict__ s2,
       __half* h0, __half* l0, __half* h1, __half* l1, __half* h2, __half* l2)
{
    const int z = blockIdx.y;
    const float* s = (z == 0) ? s0 : (z == 1) ? s1 : s2;
    __half* h = (z == 0) ? h0 : (z == 1) ? h1 : h2;
    __half* l = (z == 0) ? l0 : (z == 1) ? l1 : l2;
    const size_t i = ((size_t)blockIdx.x * 256 + threadIdx.x) * 4;
    const float4 v = *(const float4*)(s + i);
    uint32_t ha, la, hb, lb;
    split2(v.x, v.y, ha, la);
    split2(v.z, v.w, hb, lb);
    *(uint2*)(h + i) = make_uint2(ha, hb);
    if (l) *(uint2*)(l + i) = make_uint2(la, lb);
}

// ---------------- GEMM args ----------------
struct GemmArgs {
    const __half* Ah[3]; const __half* Al[3];
    const __half* Wh[3];
    const float*  bias[3];
    const float*  extra;            // MODE1: phase_scale ; MODE2: residual x
    float*  Cf [3];                 // fp32 output (or null)
    __half* Ch [3]; __half* Cl[3];  // split fp16 output (or null)
};

// ------- mma.sync GEMM: C[128,128] tile = (Ah+Al) @ Wh^T (2-pass Karatsuba) ----
// 2 CTAs/SM: bubbles of one CTA overlap with the other's MMA.
// MODE 0: v = acc + bias
// MODE 1: v = tanh(acc + bias) * extra[n]
// MODE 2: v = acc + bias + extra[row, n]
template<int MODE>
__global__ void __launch_bounds__(256, 2)
gemm_mma(GemmArgs ga)
{
    extern __shared__ char smem[];
    const int tid = threadIdx.x;
    const int z = blockIdx.z;
    const __half* Ahg = ga.Ah[z];
    const __half* Alg = ga.Al[z];
    const __half* Whg = ga.Wh[z];
    const float*  bias = ga.bias[z];

    const int bm = blockIdx.y * BM;
    const int bn = blockIdx.x * BN;
    const uint32_t sbu = smem_u32(smem);

    // ---- cp.async stage loader: Ah(16K) Al(16K) Wh(16K), 12 cp16/thread ----
    auto issue = [&](int kt, int s) {
        const uint32_t st = sbu + (uint32_t)s * STAGE_B;
        const int kof = kt * BK;
#pragma unroll
        for (int i = 0; i < 4; i++) {
            const int idx = tid + (i << 8);
            const int row = idx >> 3, c = idx & 7;
            const uint32_t so = st + (uint32_t)row * 128u
                              + (((uint32_t)c * 16u) ^ (((uint32_t)row & 7u) << 4));
            const size_t ga_ = (size_t)(bm + row) * DD + kof + c * 8;
            cp_async16(so,          Ahg + ga_);
            cp_async16(so + 16384u, Alg + ga_);
            cp_async16(so + 32768u, Whg + (size_t)(bn + row) * DD + kof + c * 8);
        }
    };

    // ---- warp compute mapping: 8 warps 4x2, warp tile 32x64 ----
    const int warp = tid >> 5, lane = tid & 31;
    const int wm0 = (warp >> 1) * 32;
    const int wn0 = (warp & 1) * 64;
    const int lr = lane & 15;
    const uint32_t lc   = ((uint32_t)lane >> 4) * 16u;
    const uint32_t xorv = ((uint32_t)lane & 7u) << 4;

    float acc[2][8][4];
#pragma unroll
    for (int mi = 0; mi < 2; mi++)
#pragma unroll
        for (int ni = 0; ni < 8; ni++)
#pragma unroll
            for (int q = 0; q < 4; q++) acc[mi][ni][q] = 0.f;

    auto compute = [&](int s) {
        const uint32_t sA = sbu + (uint32_t)s * STAGE_B;
        const uint32_t sW = sA + 32768u;
#pragma unroll
        for (int kk = 0; kk < 4; kk++) {
            const uint32_t koff = (((uint32_t)kk * 32u) + lc) ^ xorv;
            uint32_t ah[2][4], al[2][4], wh[4][4];
#pragma unroll
            for (int mi = 0; mi < 2; mi++) {
                const uint32_t rb = (uint32_t)((wm0 + mi * 16 + lr) * 128) + koff;
                ldsm4(ah[mi], sA + rb);
                ldsm4(al[mi], sA + 16384u + rb);
            }
#pragma unroll
            for (int g = 0; g < 4; g++)
                ldsm4(wh[g], sW + (uint32_t)((wn0 + g * 16 + lr) * 128) + koff);
#pragma unroll
            for (int mi = 0; mi < 2; mi++)
#pragma unroll
                for (int ni = 0; ni < 8; ni++) {
                    const uint32_t* b = wh[ni >> 1];
                    mma16816(acc[mi][ni], ah[mi], b[ni & 1], b[(ni & 1) + 2]);
                }
#pragma unroll
            for (int mi = 0; mi < 2; mi++)
#pragma unroll
                for (int ni = 0; ni < 8; ni++) {
                    const uint32_t* b = wh[ni >> 1];
                    mma16816(acc[mi][ni], al[mi], b[ni & 1], b[(ni & 1) + 2]);
                }
        }
    };

    // ---- pipeline ----
    issue(0, 0); cp_commit();
    issue(1, 1); cp_commit();
    cp_wait<1>();
    __syncthreads();
#pragma unroll 1
    for (int kt = 0; kt < NKC; kt++) {
        compute(kt & 1);
        __syncthreads();
        if (kt + 2 < NKC) issue(kt + 2, kt & 1);
        cp_commit();
        cp_wait<1>();
        __syncthreads();
    }

    // ---- epilogue ----
    const float* extra = ga.extra;
    float*  Cf = ga.Cf[z];
    __half* Ch = ga.Ch[z];
    __half* Cl = ga.Cl[z];

#pragma unroll
    for (int ni = 0; ni < 8; ni++) {
        const int c = bn + wn0 + ni * 8 + (lane & 3) * 2;
        const float b0 = bias[c], b1 = bias[c + 1];
        float p0 = 0.f, p1 = 0.f;
        if (MODE == 1) { p0 = extra[c]; p1 = extra[c + 1]; }
#pragma unroll
        for (int mi = 0; mi < 2; mi++) {
#pragma unroll
            for (int hf = 0; hf < 2; hf++) {
                const int row = bm + wm0 + mi * 16 + (lane >> 2) + hf * 8;
                float v0 = acc[mi][ni][hf * 2 + 0] + b0;
                float v1 = acc[mi][ni][hf * 2 + 1] + b1;
                if (MODE == 1) { v0 = tanhf(v0) * p0; v1 = tanhf(v1) * p1; }
                if (MODE == 2) {
                    const float2 rr = *(const float2*)(extra + (size_t)row * DD + c);
                    v0 += rr.x; v1 += rr.y;
                }
                if (Cf) *(float2*)(Cf + (size_t)row * DD + c) = make_float2(v0, v1);
                if (Ch) {
                    uint32_t h, l;
                    split2(v0, v1, h, l);
                    *(uint32_t*)(Ch + (size_t)row * DD + c) = h;
                    *(uint32_t*)(Cl + (size_t)row * DD + c) = l;
                }
            }
        }
    }
}

// ------------- fused bind + intra-chunk cumsum + retrieve + layernorm ----------
__global__ void __launch_bounds__(1024)
scan_ln(const float* __restrict__ val, const float* __restrict__ kp,
        const float* __restrict__ qp, const float* __restrict__ lng,
        const float* __restrict__ lnb, __half* __restrict__ oh, __half* __restrict__ ol)
{
    __shared__ float rs[32], rs2[32];
    __shared__ float s_mu, s_rstd;

    const int d    = threadIdx.x;
    const int lane = d & 31;
    const int wid  = d >> 5;
    const size_t base = (size_t)blockIdx.x * CHUNK * DD + d;
    const float gd = lng[d], bd = lnb[d];

    float ar = 0.f, ai = 0.f;
    for (int r = 0; r < CHUNK; r++) {
        const size_t idx = base + (size_t)r * DD;
        const float v  = val[idx];
        const float pk = kp[idx];
        const float pq = qp[idx];
        float sk, ck, sq, cq;
        sincosf(pk, &sk, &ck);
        sincosf(pq, &sq, &cq);
        ar = fmaf(v, ck, ar);
        ai = fmaf(v, sk, ai);
        const float x = (ar * cq + ai * sq) * 0.03125f;

        float s = x, s2 = x * x;
#pragma unroll
        for (int o = 16; o; o >>= 1) {
            s  += __shfl_xor_sync(0xffffffffu, s,  o);
            s2 += __shfl_xor_sync(0xffffffffu, s2, o);
        }
        if (lane == 0) { rs[wid] = s; rs2[wid] = s2; }
        __syncthreads();
        if (wid == 0) {
            s  = rs[lane];
            s2 = rs2[lane];
#pragma unroll
            for (int o = 16; o; o >>= 1) {
                s  += __shfl_xor_sync(0xffffffffu, s,  o);
                s2 += __shfl_xor_sync(0xffffffffu, s2, o);
            }
            if (lane == 0) {
                const float mu  = s * (1.f / DD);
                const float var = s2 * (1.f / DD) - mu * mu;
                s_mu   = mu;
                s_rstd = rsqrtf(var + 1e-5f);
            }
        }
        __syncthreads();
        const float y = (x - s_mu) * s_rstd * gd + bd;
        const __half h = __float2half_rn(y);
        oh[idx] = h;
        ol[idx] = __float2half_rn(y - __half2float(h));
    }
}

// --------------------------------- launch --------------------------------------
extern "C" void kernel_launch(void* const* d_in, const int* in_sizes, int n_in,
                              void* d_out, int out_size)
{
    const float* x   = (const float*)d_in[0];
    const float* Wk  = (const float*)d_in[1];
    const float* bk  = (const float*)d_in[2];
    const float* Wv  = (const float*)d_in[3];
    const float* bv  = (const float*)d_in[4];
    const float* Wq  = (const float*)d_in[5];
    const float* bq  = (const float*)d_in[6];
    const float* Wkp = (const float*)d_in[7];
    const float* bkp = (const float*)d_in[8];
    const float* Wqp = (const float*)d_in[9];
    const float* bqp = (const float*)d_in[10];
    const float* ps  = (const float*)d_in[11];
    const float* lng = (const float*)d_in[12];
    const float* lnb = (const float*)d_in[13];
    const float* Wo  = (const float*)d_in[14];
    const float* bo  = (const float*)d_in[15];
    float* out = (float*)d_out;

    __half *xh, *xl, *kh, *kl, *qh, *ql, *lnh, *lnl;
    float *val, *kpv, *qpv;
    __half (*wh)[DD * DD];
    cudaGetSymbolAddress((void**)&xh,  g_xh);
    cudaGetSymbolAddress((void**)&xl,  g_xl);
    cudaGetSymbolAddress((void**)&kh,  g_kh);
    cudaGetSymbolAddress((void**)&kl,  g_kl);
    cudaGetSymbolAddress((void**)&qh,  g_qh);
    cudaGetSymbolAddress((void**)&ql,  g_ql);
    cudaGetSymbolAddress((void**)&lnh, g_lnh);
    cudaGetSymbolAddress((void**)&lnl, g_lnl);
    cudaGetSymbolAddress((void**)&val, g_val);
    cudaGetSymbolAddress((void**)&kpv, g_kp);
    cudaGetSymbolAddress((void**)&qpv, g_qp);
    cudaGetSymbolAddress((void**)&wh,  g_wh);

    cudaFuncSetAttribute(gemm_mma<0>, cudaFuncAttributeMaxDynamicSharedMemorySize, SMEM_BYTES);
    cudaFuncSetAttribute(gemm_mma<1>, cudaFuncAttributeMaxDynamicSharedMemorySize, SMEM_BYTES);
    cudaFuncSetAttribute(gemm_mma<2>, cudaFuncAttributeMaxDynamicSharedMemorySize, SMEM_BYTES);

    // weight splits: hi only (0:Wk 1:Wv 2:Wq 3:Wkp 4:Wqp 5:Wo); x: hi+lo
    split3<<<dim3(DD * DD / 1024, 3), 256>>>(Wk, Wv, Wq,
        wh[0], nullptr, wh[1], nullptr, wh[2], nullptr);
    split3<<<dim3(DD * DD / 1024, 3), 256>>>(Wkp, Wqp, Wo,
        wh[3], nullptr, wh[4], nullptr, wh[5], nullptr);
    split3<<<dim3(MB * DD / 1024, 1), 256>>>(x, x, x, xh, xl, xh, xl, xh, xl);

    dim3 blk(256);

    // K/V/Q projections: key,qry -> split fp16 ; val -> fp32
    {
        GemmArgs a = {};
        a.Ah[0] = a.Ah[1] = a.Ah[2] = xh;
        a.Al[0] = a.Al[1] = a.Al[2] = xl;
        a.Wh[0] = wh[0]; a.bias[0] = bk;
        a.Wh[1] = wh[1]; a.bias[1] = bv;
        a.Wh[2] = wh[2]; a.bias[2] = bq;
        a.Ch[0] = kh; a.Cl[0] = kl;
        a.Cf[1] = val;
        a.Ch[2] = qh; a.Cl[2] = ql;
        gemm_mma<0><<<dim3(DD / BN, MB / BM, 3), blk, SMEM_BYTES>>>(a);
    }
    // phase projections: kp, qp fp32 (tanh * phase_scale epilogue)
    {
        GemmArgs a = {};
        a.Ah[0] = kh; a.Al[0] = kl; a.Wh[0] = wh[3]; a.bias[0] = bkp;
        a.Ah[1] = qh; a.Al[1] = ql; a.Wh[1] = wh[4]; a.bias[1] = bqp;
        a.extra = ps;
        a.Cf[0] = kpv; a.Cf[1] = qpv;
        gemm_mma<1><<<dim3(DD / BN, MB / BM, 2), blk, SMEM_BYTES>>>(a);
    }
    // bind + chunked cumsum + retrieve + layernorm -> split fp16
    scan_ln<<<MB / CHUNK, 1024>>>(val, kpv, qpv, lng, lnb, lnh, lnl);
    // output projection + residual
    {
        GemmArgs a = {};
        a.Ah[0] = lnh; a.Al[0] = lnl; a.Wh[0] = wh[5]; a.bias[0] = bo;
        a.extra = x;
        a.Cf[0] = out;
        gemm_mma<2><<<dim3(DD / BN, MB / BM, 1), blk, SMEM_BYTES>>>(a);
    }
}

// round 7
// speedup vs baseline: 5.4988x; 1.3709x over previous
#include <cuda_runtime.h>
#include <cuda_fp16.h>
#include <math.h>
#include <stdint.h>

#define DD    1024
#define MB    16384
#define CHUNK 64
#define BM    128
#define BN    128
#define BK    64
#define NKC   (DD / BK)        // 16
#define STAGE_B 49152u         // Ah 16K | Al 16K | Wh 16K
#define SMEM_BYTES (2u * STAGE_B)
#define STAGE3_B 65536u        // Ah | Al | Wh | Wl
#define SMEM3_BYTES (2u * STAGE3_B)

// ---------------- scratch (static device arrays; no allocation) ----------------
__device__ __half g_xh[MB * DD], g_xl[MB * DD];
__device__ __half g_lnh[MB * DD], g_lnl[MB * DD];
__device__ float  g_val[MB * DD];
__device__ float  g_kp [MB * DD], g_qp[MB * DD];
__device__ __half g_wv_h[DD * DD], g_wo_h[DD * DD];
__device__ __half g_wkp_h[DD * DD], g_wkp_l[DD * DD];
__device__ __half g_wqp_h[DD * DD], g_wqp_l[DD * DD];
__device__ __half g_wkt_h[DD * DD], g_wkt_l[DD * DD];
__device__ __half g_wqt_h[DD * DD], g_wqt_l[DD * DD];
__device__ __half g_wck_h[DD * DD], g_wcq_h[DD * DD];
__device__ float  g_bck[DD], g_bcq[DD];

// ---------------- helpers ----------------
__device__ __forceinline__ uint32_t smem_u32(const void* p) {
    uint32_t a;
    asm("{ .reg .u64 t; cvta.to.shared.u64 t, %1; cvt.u32.u64 %0, t; }" : "=r"(a) : "l"(p));
    return a;
}
__device__ __forceinline__ void cp_async16(uint32_t dst, const void* src) {
    asm volatile("cp.async.cg.shared.global [%0], [%1], 16;" :: "r"(dst), "l"(src));
}
__device__ __forceinline__ void cp_commit() {
    asm volatile("cp.async.commit_group;" ::: "memory");
}
template<int N>
__device__ __forceinline__ void cp_wait() {
    asm volatile("cp.async.wait_group %0;" :: "n"(N) : "memory");
}
__device__ __forceinline__ void ldsm4(uint32_t* r, uint32_t addr) {
    asm volatile("ldmatrix.sync.aligned.m8n8.x4.shared.b16 {%0,%1,%2,%3}, [%4];"
                 : "=r"(r[0]), "=r"(r[1]), "=r"(r[2]), "=r"(r[3]) : "r"(addr));
}
__device__ __forceinline__ void mma16816(float* c, const uint32_t* a, uint32_t b0, uint32_t b1) {
    asm volatile(
        "mma.sync.aligned.m16n8k16.row.col.f32.f16.f16.f32 "
        "{%0,%1,%2,%3}, {%4,%5,%6,%7}, {%8,%9}, {%0,%1,%2,%3};"
        : "+f"(c[0]), "+f"(c[1]), "+f"(c[2]), "+f"(c[3])
        : "r"(a[0]), "r"(a[1]), "r"(a[2]), "r"(a[3]), "r"(b0), "r"(b1));
}
__device__ __forceinline__ void split2(float v0, float v1, uint32_t& h, uint32_t& l) {
    __half2 hh = __floats2half2_rn(v0, v1);
    float2 f = __half22float2(hh);
    __half2 ll = __floats2half2_rn(v0 - f.x, v1 - f.y);
    h = *(uint32_t*)&hh; l = *(uint32_t*)&ll;
}

// ---------------- fp32 -> (hi fp16 [, lo fp16]) split, 3 matrices per launch ---
__global__ void __launch_bounds__(256)
split3(const float* __restrict__ s0, const float* __restrict__ s1, const float* __restrict__ s2,
       __half* h0, __half* l0, __half* h1, __half* l1, __half* h2, __half* l2)
{
    const int z = blockIdx.y;
    const float* s = (z == 0) ? s0 : (z == 1) ? s1 : s2;
    __half* h = (z == 0) ? h0 : (z == 1) ? h1 : h2;
    __half* l = (z == 0) ? l0 : (z == 1) ? l1 : l2;
    const size_t i = ((size_t)blockIdx.x * 256 + threadIdx.x) * 4;
    const float4 v = *(const float4*)(s + i);
    uint32_t ha, la, hb, lb;
    split2(v.x, v.y, ha, la);
    split2(v.z, v.w, hb, lb);
    *(uint2*)(h + i) = make_uint2(ha, hb);
    if (l) *(uint2*)(l + i) = make_uint2(la, lb);
}

// ---------------- transpose + split: out[d][m] = in[m][d] (hi+lo fp16) ---------
__global__ void __launch_bounds__(256)
tsplit(const float* __restrict__ s0, const float* __restrict__ s1,
       __half* h0, __half* l0, __half* h1, __half* l1)
{
    __shared__ float t[32][33];
    const int z = blockIdx.z;
    const float* s = z ? s1 : s0;
    __half* h = z ? h1 : h0;
    __half* l = z ? l1 : l0;
    const int bx = blockIdx.x * 32, by = blockIdx.y * 32;
    const int tx = threadIdx.x & 31, ty = threadIdx.x >> 5;
#pragma unroll
    for (int i = 0; i < 32; i += 8)
        t[ty + i][tx] = s[(size_t)(by + ty + i) * DD + bx + tx];
    __syncthreads();
#pragma unroll
    for (int i = 0; i < 32; i += 8) {
        const float v = t[tx][ty + i];
        const __half hv = __float2half_rn(v);
        const size_t o = (size_t)(bx + ty + i) * DD + by + tx;
        h[o] = hv;
        l[o] = __float2half_rn(v - __half2float(hv));
    }
}

// ---------------- bias combine: o[e] = a[e] + sum_m W[e,m] * v[m] --------------
__global__ void __launch_bounds__(256)
matvec(const float* __restrict__ W0, const float* __restrict__ v0, const float* __restrict__ a0,
       const float* __restrict__ W1, const float* __restrict__ v1, const float* __restrict__ a1,
       float* o0, float* o1)
{
    const int z = blockIdx.y;
    const float* W = z ? W1 : W0;
    const float* v = z ? v1 : v0;
    const float* a = z ? a1 : a0;
    float* o = z ? o1 : o0;
    const int e = blockIdx.x, t = threadIdx.x;
    float s = 0.f;
    for (int m = t; m < DD; m += 256)
        s += W[(size_t)e * DD + m] * v[m];
    __shared__ float r[8];
#pragma unroll
    for (int off = 16; off; off >>= 1) s += __shfl_xor_sync(0xffffffffu, s, off);
    if ((t & 31) == 0) r[t >> 5] = s;
    __syncthreads();
    if (t == 0) {
        float tot = a[e];
#pragma unroll
        for (int w = 0; w < 8; w++) tot += r[w];
        o[e] = tot;
    }
}

// ---------------- 3-pass combine GEMM: Wc[128,128] tile = A @ W^T -> hi fp16 ---
struct CombArgs {
    const __half* Ah[2]; const __half* Al[2];
    const __half* Wh[2]; const __half* Wl[2];
    __half* Ch[2];
};
__global__ void __launch_bounds__(256, 1)
gemm3p(CombArgs ga)
{
    extern __shared__ char smem[];
    const int tid = threadIdx.x;
    const int z = blockIdx.z;
    const __half* Ahg = ga.Ah[z];
    const __half* Alg = ga.Al[z];
    const __half* Whg = ga.Wh[z];
    const __half* Wlg = ga.Wl[z];

    const int bm = blockIdx.y * BM;
    const int bn = blockIdx.x * BN;
    const uint32_t sbu = smem_u32(smem);

    auto issue = [&](int kt, int s) {
        const uint32_t st = sbu + (uint32_t)s * STAGE3_B;
        const int kof = kt * BK;
#pragma unroll
        for (int i = 0; i < 4; i++) {
            const int idx = tid + (i << 8);
            const int row = idx >> 3, c = idx & 7;
            const uint32_t so = st + (uint32_t)row * 128u
                              + (((uint32_t)c * 16u) ^ (((uint32_t)row & 7u) << 4));
            const size_t gA = (size_t)(bm + row) * DD + kof + c * 8;
            const size_t gW = (size_t)(bn + row) * DD + kof + c * 8;
            cp_async16(so,          Ahg + gA);
            cp_async16(so + 16384u, Alg + gA);
            cp_async16(so + 32768u, Whg + gW);
            cp_async16(so + 49152u, Wlg + gW);
        }
    };

    const int warp = tid >> 5, lane = tid & 31;
    const int wm0 = (warp >> 1) * 32;
    const int wn0 = (warp & 1) * 64;
    const int lr = lane & 15;
    const uint32_t lc   = ((uint32_t)lane >> 4) * 16u;
    const uint32_t xorv = ((uint32_t)lane & 7u) << 4;

    float acc[2][8][4];
#pragma unroll
    for (int mi = 0; mi < 2; mi++)
#pragma unroll
        for (int ni = 0; ni < 8; ni++)
#pragma unroll
            for (int q = 0; q < 4; q++) acc[mi][ni][q] = 0.f;

    auto compute = [&](int s) {
        const uint32_t sA = sbu + (uint32_t)s * STAGE3_B;
        const uint32_t sW = sA + 32768u;
#pragma unroll
        for (int kk = 0; kk < 4; kk++) {
            const uint32_t koff = (((uint32_t)kk * 32u) + lc) ^ xorv;
            uint32_t ah[2][4], al[2][4], wh[4][4], wl[4][4];
#pragma unroll
            for (int mi = 0; mi < 2; mi++) {
                const uint32_t rb = (uint32_t)((wm0 + mi * 16 + lr) * 128) + koff;
                ldsm4(ah[mi], sA + rb);
                ldsm4(al[mi], sA + 16384u + rb);
            }
#pragma unroll
            for (int g = 0; g < 4; g++) {
                const uint32_t rb = (uint32_t)((wn0 + g * 16 + lr) * 128) + koff;
                ldsm4(wh[g], sW + rb);
                ldsm4(wl[g], sW + 16384u + rb);
            }
#pragma unroll
            for (int mi = 0; mi < 2; mi++)
#pragma unroll
                for (int ni = 0; ni < 8; ni++) {
                    const uint32_t* b = wh[ni >> 1];
                    mma16816(acc[mi][ni], ah[mi], b[ni & 1], b[(ni & 1) + 2]);
                }
#pragma unroll
            for (int mi = 0; mi < 2; mi++)
#pragma unroll
                for (int ni = 0; ni < 8; ni++) {
                    const uint32_t* b = wh[ni >> 1];
                    mma16816(acc[mi][ni], al[mi], b[ni & 1], b[(ni & 1) + 2]);
                }
#pragma unroll
            for (int mi = 0; mi < 2; mi++)
#pragma unroll
                for (int ni = 0; ni < 8; ni++) {
                    const uint32_t* b = wl[ni >> 1];
                    mma16816(acc[mi][ni], ah[mi], b[ni & 1], b[(ni & 1) + 2]);
                }
        }
    };

    issue(0, 0); cp_commit();
    issue(1, 1); cp_commit();
    cp_wait<1>();
    __syncthreads();
#pragma unroll 1
    for (int kt = 0; kt < NKC; kt++) {
        compute(kt & 1);
        __syncthreads();
        if (kt + 2 < NKC) issue(kt + 2, kt & 1);
        cp_commit();
        cp_wait<1>();
        __syncthreads();
    }

    __half* Ch = ga.Ch[z];
#pragma unroll
    for (int ni = 0; ni < 8; ni++) {
        const int c = bn + wn0 + ni * 8 + (lane & 3) * 2;
#pragma unroll
        for (int mi = 0; mi < 2; mi++) {
#pragma unroll
            for (int hf = 0; hf < 2; hf++) {
                const int row = bm + wm0 + mi * 16 + (lane >> 2) + hf * 8;
                __half2 hv = __floats2half2_rn(acc[mi][ni][hf * 2], acc[mi][ni][hf * 2 + 1]);
                *(__half2*)(Ch + (size_t)row * DD + c) = hv;
            }
        }
    }
}

// ---------------- GEMM args (runtime per-slice epilogue mode) ------------------
struct GemmArgs {
    const __half* Ah[3]; const __half* Al[3];
    const __half* Wh[3];
    const float*  bias[3];
    const float*  extra[3];         // mode1: phase_scale ; mode2: residual x
    float*  Cf [3];
    __half* Ch [3]; __half* Cl[3];
    int mode[3];
};

// ------- 2-pass mma GEMM: C[128,128] tile = (Ah+Al) @ Wh^T ---------------------
__global__ void __launch_bounds__(256, 2)
gemm2p(GemmArgs ga)
{
    extern __shared__ char smem[];
    const int tid = threadIdx.x;
    const int z = blockIdx.z;
    const __half* Ahg = ga.Ah[z];
    const __half* Alg = ga.Al[z];
    const __half* Whg = ga.Wh[z];
    const float*  bias = ga.bias[z];

    const int bm = blockIdx.y * BM;
    const int bn = blockIdx.x * BN;
    const uint32_t sbu = smem_u32(smem);

    auto issue = [&](int kt, int s) {
        const uint32_t st = sbu + (uint32_t)s * STAGE_B;
        const int kof = kt * BK;
#pragma unroll
        for (int i = 0; i < 4; i++) {
            const int idx = tid + (i << 8);
            const int row = idx >> 3, c = idx & 7;
            const uint32_t so = st + (uint32_t)row * 128u
                              + (((uint32_t)c * 16u) ^ (((uint32_t)row & 7u) << 4));
            const size_t ga_ = (size_t)(bm + row) * DD + kof + c * 8;
            cp_async16(so,          Ahg + ga_);
            cp_async16(so + 16384u, Alg + ga_);
            cp_async16(so + 32768u, Whg + (size_t)(bn + row) * DD + kof + c * 8);
        }
    };

    const int warp = tid >> 5, lane = tid & 31;
    const int wm0 = (warp >> 1) * 32;
    const int wn0 = (warp & 1) * 64;
    const int lr = lane & 15;
    const uint32_t lc   = ((uint32_t)lane >> 4) * 16u;
    const uint32_t xorv = ((uint32_t)lane & 7u) << 4;

    float acc[2][8][4];
#pragma unroll
    for (int mi = 0; mi < 2; mi++)
#pragma unroll
        for (int ni = 0; ni < 8; ni++)
#pragma unroll
            for (int q = 0; q < 4; q++) acc[mi][ni][q] = 0.f;

    auto compute = [&](int s) {
        const uint32_t sA = sbu + (uint32_t)s * STAGE_B;
        const uint32_t sW = sA + 32768u;
#pragma unroll
        for (int kk = 0; kk < 4; kk++) {
            const uint32_t koff = (((uint32_t)kk * 32u) + lc) ^ xorv;
            uint32_t ah[2][4], al[2][4], wh[4][4];
#pragma unroll
            for (int mi = 0; mi < 2; mi++) {
                const uint32_t rb = (uint32_t)((wm0 + mi * 16 + lr) * 128) + koff;
                ldsm4(ah[mi], sA + rb);
                ldsm4(al[mi], sA + 16384u + rb);
            }
#pragma unroll
            for (int g = 0; g < 4; g++)
                ldsm4(wh[g], sW + (uint32_t)((wn0 + g * 16 + lr) * 128) + koff);
#pragma unroll
            for (int mi = 0; mi < 2; mi++)
#pragma unroll
                for (int ni = 0; ni < 8; ni++) {
                    const uint32_t* b = wh[ni >> 1];
                    mma16816(acc[mi][ni], ah[mi], b[ni & 1], b[(ni & 1) + 2]);
                }
#pragma unroll
            for (int mi = 0; mi < 2; mi++)
#pragma unroll
                for (int ni = 0; ni < 8; ni++) {
                    const uint32_t* b = wh[ni >> 1];
                    mma16816(acc[mi][ni], al[mi], b[ni & 1], b[(ni & 1) + 2]);
                }
        }
    };

    issue(0, 0); cp_commit();
    issue(1, 1); cp_commit();
    cp_wait<1>();
    __syncthreads();
#pragma unroll 1
    for (int kt = 0; kt < NKC; kt++) {
        compute(kt & 1);
        __syncthreads();
        if (kt + 2 < NKC) issue(kt + 2, kt & 1);
        cp_commit();
        cp_wait<1>();
        __syncthreads();
    }

    // ---- epilogue ----
    const int mode = ga.mode[z];
    const float* extra = ga.extra[z];
    float*  Cf = ga.Cf[z];
    __half* Ch = ga.Ch[z];
    __half* Cl = ga.Cl[z];

#pragma unroll
    for (int ni = 0; ni < 8; ni++) {
        const int c = bn + wn0 + ni * 8 + (lane & 3) * 2;
        const float b0 = bias[c], b1 = bias[c + 1];
        float p0 = 0.f, p1 = 0.f;
        if (mode == 1) { p0 = extra[c]; p1 = extra[c + 1]; }
#pragma unroll
        for (int mi = 0; mi < 2; mi++) {
#pragma unroll
            for (int hf = 0; hf < 2; hf++) {
                const int row = bm + wm0 + mi * 16 + (lane >> 2) + hf * 8;
                float v0 = acc[mi][ni][hf * 2 + 0] + b0;
                float v1 = acc[mi][ni][hf * 2 + 1] + b1;
                if (mode == 1) { v0 = tanhf(v0) * p0; v1 = tanhf(v1) * p1; }
                if (mode == 2) {
                    const float2 rr = *(const float2*)(extra + (size_t)row * DD + c);
                    v0 += rr.x; v1 += rr.y;
                }
                if (Cf) *(float2*)(Cf + (size_t)row * DD + c) = make_float2(v0, v1);
                if (Ch) {
                    uint32_t h, l;
                    split2(v0, v1, h, l);
                    *(uint32_t*)(Ch + (size_t)row * DD + c) = h;
                    *(uint32_t*)(Cl + (size_t)row * DD + c) = l;
                }
            }
        }
    }
}

// ------------- fused bind + intra-chunk cumsum + retrieve + layernorm ----------
__global__ void __launch_bounds__(1024)
scan_ln(const float* __restrict__ val, const float* __restrict__ kp,
        const float* __restrict__ qp, const float* __restrict__ lng,
        const float* __restrict__ lnb, __half* __restrict__ oh, __half* __restrict__ ol)
{
    __shared__ float rs[32], rs2[32];
    __shared__ float s_mu, s_rstd;

    const int d    = threadIdx.x;
    const int lane = d & 31;
    const int wid  = d >> 5;
    const size_t base = (size_t)blockIdx.x * CHUNK * DD + d;
    const float gd = lng[d], bd = lnb[d];

    float ar = 0.f, ai = 0.f;
    for (int r = 0; r < CHUNK; r++) {
        const size_t idx = base + (size_t)r * DD;
        const float v  = val[idx];
        const float pk = kp[idx];
        const float pq = qp[idx];
        float sk, ck, sq, cq;
        sincosf(pk, &sk, &ck);
        sincosf(pq, &sq, &cq);
        ar = fmaf(v, ck, ar);
        ai = fmaf(v, sk, ai);
        const float x = (ar * cq + ai * sq) * 0.03125f;

        float s = x, s2 = x * x;
#pragma unroll
        for (int o = 16; o; o >>= 1) {
            s  += __shfl_xor_sync(0xffffffffu, s,  o);
            s2 += __shfl_xor_sync(0xffffffffu, s2, o);
        }
        if (lane == 0) { rs[wid] = s; rs2[wid] = s2; }
        __syncthreads();
        if (wid == 0) {
            s  = rs[lane];
            s2 = rs2[lane];
#pragma unroll
            for (int o = 16; o; o >>= 1) {
                s  += __shfl_xor_sync(0xffffffffu, s,  o);
                s2 += __shfl_xor_sync(0xffffffffu, s2, o);
            }
            if (lane == 0) {
                const float mu  = s * (1.f / DD);
                const float var = s2 * (1.f / DD) - mu * mu;
                s_mu   = mu;
                s_rstd = rsqrtf(var + 1e-5f);
            }
        }
        __syncthreads();
        const float y = (x - s_mu) * s_rstd * gd + bd;
        const __half h = __float2half_rn(y);
        oh[idx] = h;
        ol[idx] = __float2half_rn(y - __half2float(h));
    }
}

// --------------------------------- launch --------------------------------------
extern "C" void kernel_launch(void* const* d_in, const int* in_sizes, int n_in,
                              void* d_out, int out_size)
{
    const float* x   = (const float*)d_in[0];
    const float* Wk  = (const float*)d_in[1];
    const float* bk  = (const float*)d_in[2];
    const float* Wv  = (const float*)d_in[3];
    const float* bv  = (const float*)d_in[4];
    const float* Wq  = (const float*)d_in[5];
    const float* bq  = (const float*)d_in[6];
    const float* Wkp = (const float*)d_in[7];
    const float* bkp = (const float*)d_in[8];
    const float* Wqp = (const float*)d_in[9];
    const float* bqp = (const float*)d_in[10];
    const float* ps  = (const float*)d_in[11];
    const float* lng = (const float*)d_in[12];
    const float* lnb = (const float*)d_in[13];
    const float* Wo  = (const float*)d_in[14];
    const float* bo  = (const float*)d_in[15];
    float* out = (float*)d_out;

    __half *xh, *xl, *lnh, *lnl;
    __half *wv_h, *wo_h, *wkp_h, *wkp_l, *wqp_h, *wqp_l;
    __half *wkt_h, *wkt_l, *wqt_h, *wqt_l, *wck_h, *wcq_h;
    float *val, *kpv, *qpv, *bck, *bcq;
    cudaGetSymbolAddress((void**)&xh,    g_xh);
    cudaGetSymbolAddress((void**)&xl,    g_xl);
    cudaGetSymbolAddress((void**)&lnh,   g_lnh);
    cudaGetSymbolAddress((void**)&lnl,   g_lnl);
    cudaGetSymbolAddress((void**)&val,   g_val);
    cudaGetSymbolAddress((void**)&kpv,   g_kp);
    cudaGetSymbolAddress((void**)&qpv,   g_qp);
    cudaGetSymbolAddress((void**)&wv_h,  g_wv_h);
    cudaGetSymbolAddress((void**)&wo_h,  g_wo_h);
    cudaGetSymbolAddress((void**)&wkp_h, g_wkp_h);
    cudaGetSymbolAddress((void**)&wkp_l, g_wkp_l);
    cudaGetSymbolAddress((void**)&wqp_h, g_wqp_h);
    cudaGetSymbolAddress((void**)&wqp_l, g_wqp_l);
    cudaGetSymbolAddress((void**)&wkt_h, g_wkt_h);
    cudaGetSymbolAddress((void**)&wkt_l, g_wkt_l);
    cudaGetSymbolAddress((void**)&wqt_h, g_wqt_h);
    cudaGetSymbolAddress((void**)&wqt_l, g_wqt_l);
    cudaGetSymbolAddress((void**)&wck_h, g_wck_h);
    cudaGetSymbolAddress((void**)&wcq_h, g_wcq_h);
    cudaGetSymbolAddress((void**)&bck,   g_bck);
    cudaGetSymbolAddress((void**)&bcq,   g_bcq);

    cudaFuncSetAttribute(gemm2p, cudaFuncAttributeMaxDynamicSharedMemorySize, SMEM_BYTES);
    cudaFuncSetAttribute(gemm3p, cudaFuncAttributeMaxDynamicSharedMemorySize, SMEM3_BYTES);

    // splits: Wv(hi), Wkp(hi+lo), Wqp(hi+lo) | Wo(hi) | x(hi+lo)
    split3<<<dim3(DD * DD / 1024, 3), 256>>>(Wv, Wkp, Wqp,
        wv_h, nullptr, wkp_h, wkp_l, wqp_h, wqp_l);
    split3<<<dim3(DD * DD / 1024, 1), 256>>>(Wo, Wo, Wo,
        wo_h, nullptr, nullptr, nullptr, nullptr, nullptr);
    split3<<<dim3(MB * DD / 1024, 1), 256>>>(x, x, x,
        xh, xl, nullptr, nullptr, nullptr, nullptr);
    // transposed splits of Wk, Wq (W-side of the combine)
    tsplit<<<dim3(32, 32, 2), 256>>>(Wk, Wq, wkt_h, wkt_l, wqt_h, wqt_l);
    // combined biases: bck = Wkp*bk + bkp ; bcq = Wqp*bq + bqp
    matvec<<<dim3(DD, 2), 256>>>(Wkp, bk, bkp, Wqp, bq, bqp, bck, bcq);

    // combined weights: Wck = Wkp*Wk, Wcq = Wqp*Wq  (3-pass, hi fp16 out)
    {
        CombArgs a = {};
        a.Ah[0] = wkp_h; a.Al[0] = wkp_l; a.Wh[0] = wkt_h; a.Wl[0] = wkt_l; a.Ch[0] = wck_h;
        a.Ah[1] = wqp_h; a.Al[1] = wqp_l; a.Wh[1] = wqt_h; a.Wl[1] = wqt_l; a.Ch[1] = wcq_h;
        gemm3p<<<dim3(DD / BN, DD / BM, 2), 256, SMEM3_BYTES>>>(a);
    }

    // fused big GEMM: z0 value (mode0), z1 key_phase (mode1), z2 query_phase (mode1)
    {
        GemmArgs a = {};
        a.Ah[0] = a.Ah[1] = a.Ah[2] = xh;
        a.Al[0] = a.Al[1] = a.Al[2] = xl;
        a.Wh[0] = wv_h;  a.bias[0] = bv;  a.mode[0] = 0; a.Cf[0] = val;
        a.Wh[1] = wck_h; a.bias[1] = bck; a.mode[1] = 1; a.Cf[1] = kpv; a.extra[1] = ps;
        a.Wh[2] = wcq_h; a.bias[2] = bcq; a.mode[2] = 1; a.Cf[2] = qpv; a.extra[2] = ps;
        gemm2p<<<dim3(DD / BN, MB / BM, 3), 256, SMEM_BYTES>>>(a);
    }
    // bind + chunked cumsum + retrieve + layernorm -> split fp16
    scan_ln<<<MB / CHUNK, 1024>>>(val, kpv, qpv, lng, lnb, lnh, lnl);
    // output projection + residual
    {
        GemmArgs a = {};
        a.Ah[0] = lnh; a.Al[0] = lnl; a.Wh[0] = wo_h; a.bias[0] = bo;
        a.mode[0] = 2; a.extra[0] = x; a.Cf[0] = out;
        gemm2p<<<dim3(DD / BN, MB / BM, 1), 256, SMEM_BYTES>>>(a);
    }
}

// round 8
// speedup vs baseline: 8.3244x; 1.5139x over previous
#include <cuda_runtime.h>
#include <cuda_fp16.h>
#include <math.h>
#include <stdint.h>

#define DD    1024
#define MB    16384
#define CHUNK 64
#define BM    128
#define BN    128
#define BK    64
#define NKC   (DD / BK)        // 16
#define STAGE_B 32768u         // Ah 16K | Wh 16K
#define NSTG  3
#define SMEM_BYTES (NSTG * STAGE_B)
#define STAGE3_B 65536u        // combine: Ah | Al | Wh | Wl
#define SMEM3_BYTES (2u * STAGE3_B)

// ---------------- scratch (static device arrays; no allocation) ----------------
__device__ __half g_xh[MB * DD];
__device__ __half g_lnh[MB * DD];
__device__ float  g_val[MB * DD];
__device__ float  g_kp [MB * DD], g_qp[MB * DD];
__device__ __half g_wv_h[DD * DD], g_wo_h[DD * DD];
__device__ __half g_wkp_h[DD * DD], g_wkp_l[DD * DD];
__device__ __half g_wqp_h[DD * DD], g_wqp_l[DD * DD];
__device__ __half g_wkt_h[DD * DD], g_wkt_l[DD * DD];
__device__ __half g_wqt_h[DD * DD], g_wqt_l[DD * DD];
__device__ __half g_wck_h[DD * DD], g_wcq_h[DD * DD];
__device__ float  g_bck[DD], g_bcq[DD];

// ---------------- helpers ----------------
__device__ __forceinline__ uint32_t smem_u32(const void* p) {
    uint32_t a;
    asm("{ .reg .u64 t; cvta.to.shared.u64 t, %1; cvt.u32.u64 %0, t; }" : "=r"(a) : "l"(p));
    return a;
}
__device__ __forceinline__ void cp_async16(uint32_t dst, const void* src) {
    asm volatile("cp.async.cg.shared.global [%0], [%1], 16;" :: "r"(dst), "l"(src));
}
__device__ __forceinline__ void cp_commit() {
    asm volatile("cp.async.commit_group;" ::: "memory");
}
template<int N>
__device__ __forceinline__ void cp_wait() {
    asm volatile("cp.async.wait_group %0;" :: "n"(N) : "memory");
}
__device__ __forceinline__ void ldsm4(uint32_t* r, uint32_t addr) {
    asm volatile("ldmatrix.sync.aligned.m8n8.x4.shared.b16 {%0,%1,%2,%3}, [%4];"
                 : "=r"(r[0]), "=r"(r[1]), "=r"(r[2]), "=r"(r[3]) : "r"(addr));
}
__device__ __forceinline__ void mma16816(float* c, const uint32_t* a, uint32_t b0, uint32_t b1) {
    asm volatile(
        "mma.sync.aligned.m16n8k16.row.col.f32.f16.f16.f32 "
        "{%0,%1,%2,%3}, {%4,%5,%6,%7}, {%8,%9}, {%0,%1,%2,%3};"
        : "+f"(c[0]), "+f"(c[1]), "+f"(c[2]), "+f"(c[3])
        : "r"(a[0]), "r"(a[1]), "r"(a[2]), "r"(a[3]), "r"(b0), "r"(b1));
}
__device__ __forceinline__ void split2(float v0, float v1, uint32_t& h, uint32_t& l) {
    __half2 hh = __floats2half2_rn(v0, v1);
    float2 f = __half22float2(hh);
    __half2 ll = __floats2half2_rn(v0 - f.x, v1 - f.y);
    h = *(uint32_t*)&hh; l = *(uint32_t*)&ll;
}

// ---------------- fp32 -> (hi fp16 [, lo fp16]) split, 3 matrices per launch ---
__global__ void __launch_bounds__(256)
split3(const float* __restrict__ s0, const float* __restrict__ s1, const float* __restrict__ s2,
       __half* h0, __half* l0, __half* h1, __half* l1, __half* h2, __half* l2)
{
    const int z = blockIdx.y;
    const float* s = (z == 0) ? s0 : (z == 1) ? s1 : s2;
    __half* h = (z == 0) ? h0 : (z == 1) ? h1 : h2;
    __half* l = (z == 0) ? l0 : (z == 1) ? l1 : l2;
    const size_t i = ((size_t)blockIdx.x * 256 + threadIdx.x) * 4;
    const float4 v = *(const float4*)(s + i);
    uint32_t ha, la, hb, lb;
    split2(v.x, v.y, ha, la);
    split2(v.z, v.w, hb, lb);
    *(uint2*)(h + i) = make_uint2(ha, hb);
    if (l) *(uint2*)(l + i) = make_uint2(la, lb);
}

// ---------------- transpose + split: out[d][m] = in[m][d] (hi+lo fp16) ---------
__global__ void __launch_bounds__(256)
tsplit(const float* __restrict__ s0, const float* __restrict__ s1,
       __half* h0, __half* l0, __half* h1, __half* l1)
{
    __shared__ float t[32][33];
    const int z = blockIdx.z;
    const float* s = z ? s1 : s0;
    __half* h = z ? h1 : h0;
    __half* l = z ? l1 : l0;
    const int bx = blockIdx.x * 32, by = blockIdx.y * 32;
    const int tx = threadIdx.x & 31, ty = threadIdx.x >> 5;
#pragma unroll
    for (int i = 0; i < 32; i += 8)
        t[ty + i][tx] = s[(size_t)(by + ty + i) * DD + bx + tx];
    __syncthreads();
#pragma unroll
    for (int i = 0; i < 32; i += 8) {
        const float v = t[tx][ty + i];
        const __half hv = __float2half_rn(v);
        const size_t o = (size_t)(bx + ty + i) * DD + by + tx;
        h[o] = hv;
        l[o] = __float2half_rn(v - __half2float(hv));
    }
}

// ---------------- bias combine: o[e] = a[e] + sum_m W[e,m] * v[m] --------------
__global__ void __launch_bounds__(256)
matvec(const float* __restrict__ W0, const float* __restrict__ v0, const float* __restrict__ a0,
       const float* __restrict__ W1, const float* __restrict__ v1, const float* __restrict__ a1,
       float* o0, float* o1)
{
    const int z = blockIdx.y;
    const float* W = z ? W1 : W0;
    const float* v = z ? v1 : v0;
    const float* a = z ? a1 : a0;
    float* o = z ? o1 : o0;
    const int e = blockIdx.x, t = threadIdx.x;
    float s = 0.f;
    for (int m = t; m < DD; m += 256)
        s += W[(size_t)e * DD + m] * v[m];
    __shared__ float r[8];
#pragma unroll
    for (int off = 16; off; off >>= 1) s += __shfl_xor_sync(0xffffffffu, s, off);
    if ((t & 31) == 0) r[t >> 5] = s;
    __syncthreads();
    if (t == 0) {
        float tot = a[e];
#pragma unroll
        for (int w = 0; w < 8; w++) tot += r[w];
        o[e] = tot;
    }
}

// ---------------- 3-pass combine GEMM: Wc[128,128] tile = A @ W^T -> hi fp16 ---
struct CombArgs {
    const __half* Ah[2]; const __half* Al[2];
    const __half* Wh[2]; const __half* Wl[2];
    __half* Ch[2];
};
__global__ void __launch_bounds__(256, 1)
gemm3p(CombArgs ga)
{
    extern __shared__ char smem[];
    const int tid = threadIdx.x;
    const int z = blockIdx.z;
    const __half* Ahg = ga.Ah[z];
    const __half* Alg = ga.Al[z];
    const __half* Whg = ga.Wh[z];
    const __half* Wlg = ga.Wl[z];

    const int bm = blockIdx.y * BM;
    const int bn = blockIdx.x * BN;
    const uint32_t sbu = smem_u32(smem);

    auto issue = [&](int kt, int s) {
        const uint32_t st = sbu + (uint32_t)s * STAGE3_B;
        const int kof = kt * BK;
#pragma unroll
        for (int i = 0; i < 4; i++) {
            const int idx = tid + (i << 8);
            const int row = idx >> 3, c = idx & 7;
            const uint32_t so = st + (uint32_t)row * 128u
                              + (((uint32_t)c * 16u) ^ (((uint32_t)row & 7u) << 4));
            const size_t gA = (size_t)(bm + row) * DD + kof + c * 8;
            const size_t gW = (size_t)(bn + row) * DD + kof + c * 8;
            cp_async16(so,          Ahg + gA);
            cp_async16(so + 16384u, Alg + gA);
            cp_async16(so + 32768u, Whg + gW);
            cp_async16(so + 49152u, Wlg + gW);
        }
    };

    const int warp = tid >> 5, lane = tid & 31;
    const int wm0 = (warp >> 1) * 32;
    const int wn0 = (warp & 1) * 64;
    const int lr = lane & 15;
    const uint32_t lc   = ((uint32_t)lane >> 4) * 16u;
    const uint32_t xorv = ((uint32_t)lane & 7u) << 4;

    float acc[2][8][4];
#pragma unroll
    for (int mi = 0; mi < 2; mi++)
#pragma unroll
        for (int ni = 0; ni < 8; ni++)
#pragma unroll
            for (int q = 0; q < 4; q++) acc[mi][ni][q] = 0.f;

    auto compute = [&](int s) {
        const uint32_t sA = sbu + (uint32_t)s * STAGE3_B;
        const uint32_t sW = sA + 32768u;
#pragma unroll
        for (int kk = 0; kk < 4; kk++) {
            const uint32_t koff = (((uint32_t)kk * 32u) + lc) ^ xorv;
            uint32_t ah[2][4], al[2][4], wh[4][4], wl[4][4];
#pragma unroll
            for (int mi = 0; mi < 2; mi++) {
                const uint32_t rb = (uint32_t)((wm0 + mi * 16 + lr) * 128) + koff;
                ldsm4(ah[mi], sA + rb);
                ldsm4(al[mi], sA + 16384u + rb);
            }
#pragma unroll
            for (int g = 0; g < 4; g++) {
                const uint32_t rb = (uint32_t)((wn0 + g * 16 + lr) * 128) + koff;
                ldsm4(wh[g], sW + rb);
                ldsm4(wl[g], sW + 16384u + rb);
            }
#pragma unroll
            for (int mi = 0; mi < 2; mi++)
#pragma unroll
                for (int ni = 0; ni < 8; ni++) {
                    const uint32_t* b = wh[ni >> 1];
                    mma16816(acc[mi][ni], ah[mi], b[ni & 1], b[(ni & 1) + 2]);
                }
#pragma unroll
            for (int mi = 0; mi < 2; mi++)
#pragma unroll
                for (int ni = 0; ni < 8; ni++) {
                    const uint32_t* b = wh[ni >> 1];
                    mma16816(acc[mi][ni], al[mi], b[ni & 1], b[(ni & 1) + 2]);
                }
#pragma unroll
            for (int mi = 0; mi < 2; mi++)
#pragma unroll
                for (int ni = 0; ni < 8; ni++) {
                    const uint32_t* b = wl[ni >> 1];
                    mma16816(acc[mi][ni], ah[mi], b[ni & 1], b[(ni & 1) + 2]);
                }
        }
    };

    issue(0, 0); cp_commit();
    issue(1, 1); cp_commit();
    cp_wait<1>();
    __syncthreads();
#pragma unroll 1
    for (int kt = 0; kt < NKC; kt++) {
        compute(kt & 1);
        __syncthreads();
        if (kt + 2 < NKC) issue(kt + 2, kt & 1);
        cp_commit();
        cp_wait<1>();
        __syncthreads();
    }

    __half* Ch = ga.Ch[z];
#pragma unroll
    for (int ni = 0; ni < 8; ni++) {
        const int c = bn + wn0 + ni * 8 + (lane & 3) * 2;
#pragma unroll
        for (int mi = 0; mi < 2; mi++) {
#pragma unroll
            for (int hf = 0; hf < 2; hf++) {
                const int row = bm + wm0 + mi * 16 + (lane >> 2) + hf * 8;
                __half2 hv = __floats2half2_rn(acc[mi][ni][hf * 2], acc[mi][ni][hf * 2 + 1]);
                *(__half2*)(Ch + (size_t)row * DD + c) = hv;
            }
        }
    }
}

// ---------------- GEMM args (runtime per-slice epilogue mode) ------------------
struct GemmArgs {
    const __half* Ah[3];
    const __half* Wh[3];
    const float*  bias[3];
    const float*  extra[3];         // mode1: phase_scale ; mode2: residual x
    float*  Cf[3];
    int mode[3];
};

// ------- 1-pass mma GEMM: C[128,128] tile = Ah @ Wh^T, 3-stage pipeline --------
__global__ void __launch_bounds__(256, 2)
gemm1p(GemmArgs ga)
{
    extern __shared__ char smem[];
    const int tid = threadIdx.x;
    const int z = blockIdx.z;
    const __half* Ahg = ga.Ah[z];
    const __half* Whg = ga.Wh[z];
    const float*  bias = ga.bias[z];

    const int bm = blockIdx.y * BM;
    const int bn = blockIdx.x * BN;
    const uint32_t sbu = smem_u32(smem);

    // ---- cp.async stage loader: Ah(16K) Wh(16K), 8 cp16/thread ----
    auto issue = [&](int kt, int s) {
        const uint32_t st = sbu + (uint32_t)s * STAGE_B;
        const int kof = kt * BK;
#pragma unroll
        for (int i = 0; i < 4; i++) {
            const int idx = tid + (i << 8);
            const int row = idx >> 3, c = idx & 7;
            const uint32_t so = st + (uint32_t)row * 128u
                              + (((uint32_t)c * 16u) ^ (((uint32_t)row & 7u) << 4));
            cp_async16(so,          Ahg + (size_t)(bm + row) * DD + kof + c * 8);
            cp_async16(so + 16384u, Whg + (size_t)(bn + row) * DD + kof + c * 8);
        }
    };

    // ---- warp compute mapping: 8 warps 4x2, warp tile 32x64 ----
    const int warp = tid >> 5, lane = tid & 31;
    const int wm0 = (warp >> 1) * 32;
    const int wn0 = (warp & 1) * 64;
    const int lr = lane & 15;
    const uint32_t lc   = ((uint32_t)lane >> 4) * 16u;
    const uint32_t xorv = ((uint32_t)lane & 7u) << 4;

    float acc[2][8][4];
#pragma unroll
    for (int mi = 0; mi < 2; mi++)
#pragma unroll
        for (int ni = 0; ni < 8; ni++)
#pragma unroll
            for (int q = 0; q < 4; q++) acc[mi][ni][q] = 0.f;

    auto compute = [&](int s) {
        const uint32_t sA = sbu + (uint32_t)s * STAGE_B;
        const uint32_t sW = sA + 16384u;
#pragma unroll
        for (int kk = 0; kk < 4; kk++) {
            const uint32_t koff = (((uint32_t)kk * 32u) + lc) ^ xorv;
            uint32_t ah[2][4], wh[4][4];
#pragma unroll
            for (int mi = 0; mi < 2; mi++)
                ldsm4(ah[mi], sA + (uint32_t)((wm0 + mi * 16 + lr) * 128) + koff);
#pragma unroll
            for (int g = 0; g < 4; g++)
                ldsm4(wh[g], sW + (uint32_t)((wn0 + g * 16 + lr) * 128) + koff);
#pragma unroll
            for (int mi = 0; mi < 2; mi++)
#pragma unroll
                for (int ni = 0; ni < 8; ni++) {
                    const uint32_t* b = wh[ni >> 1];
                    mma16816(acc[mi][ni], ah[mi], b[ni & 1], b[(ni & 1) + 2]);
                }
        }
    };

    // ---- 3-stage pipeline, one __syncthreads per chunk ----
    issue(0, 0); cp_commit();
    issue(1, 1); cp_commit();
#pragma unroll 1
    for (int kt = 0; kt < NKC; kt++) {
        cp_wait<1>();
        __syncthreads();
        // overwrites stage consumed at chunk kt-1 (all warps past it per the sync)
        if (kt + 2 < NKC) issue(kt + 2, (kt + 2) % NSTG);
        cp_commit();
        compute(kt % NSTG);
    }

    // ---- epilogue ----
    const int mode = ga.mode[z];
    const float* extra = ga.extra[z];
    float* Cf = ga.Cf[z];

#pragma unroll
    for (int ni = 0; ni < 8; ni++) {
        const int c = bn + wn0 + ni * 8 + (lane & 3) * 2;
        const float b0 = bias[c], b1 = bias[c + 1];
        float p0 = 0.f, p1 = 0.f;
        if (mode == 1) { p0 = extra[c]; p1 = extra[c + 1]; }
#pragma unroll
        for (int mi = 0; mi < 2; mi++) {
#pragma unroll
            for (int hf = 0; hf < 2; hf++) {
                const int row = bm + wm0 + mi * 16 + (lane >> 2) + hf * 8;
                float v0 = acc[mi][ni][hf * 2 + 0] + b0;
                float v1 = acc[mi][ni][hf * 2 + 1] + b1;
                if (mode == 1) { v0 = tanhf(v0) * p0; v1 = tanhf(v1) * p1; }
                if (mode == 2) {
                    const float2 rr = *(const float2*)(extra + (size_t)row * DD + c);
                    v0 += rr.x; v1 += rr.y;
                }
                *(float2*)(Cf + (size_t)row * DD + c) = make_float2(v0, v1);
            }
        }
    }
}

// ------------- fused bind + intra-chunk cumsum + retrieve + layernorm ----------
__global__ void __launch_bounds__(1024)
scan_ln(const float* __restrict__ val, const float* __restrict__ kp,
        const float* __restrict__ qp, const float* __restrict__ lng,
        const float* __restrict__ lnb, __half* __restrict__ oh)
{
    __shared__ float rs[32], rs2[32];
    __shared__ float s_mu, s_rstd;

    const int d    = threadIdx.x;
    const int lane = d & 31;
    const int wid  = d >> 5;
    const size_t base = (size_t)blockIdx.x * CHUNK * DD + d;
    const float gd = lng[d], bd = lnb[d];

    float ar = 0.f, ai = 0.f;
    for (int r = 0; r < CHUNK; r++) {
        const size_t idx = base + (size_t)r * DD;
        const float v  = val[idx];
        const float pk = kp[idx];
        const float pq = qp[idx];
        float sk, ck, sq, cq;
        sincosf(pk, &sk, &ck);
        sincosf(pq, &sq, &cq);
        ar = fmaf(v, ck, ar);
        ai = fmaf(v, sk, ai);
        const float x = (ar * cq + ai * sq) * 0.03125f;

        float s = x, s2 = x * x;
#pragma unroll
        for (int o = 16; o; o >>= 1) {
            s  += __shfl_xor_sync(0xffffffffu, s,  o);
            s2 += __shfl_xor_sync(0xffffffffu, s2, o);
        }
        if (lane == 0) { rs[wid] = s; rs2[wid] = s2; }
        __syncthreads();
        if (wid == 0) {
            s  = rs[lane];
            s2 = rs2[lane];
#pragma unroll
            for (int o = 16; o; o >>= 1) {
                s  += __shfl_xor_sync(0xffffffffu, s,  o);
                s2 += __shfl_xor_sync(0xffffffffu, s2, o);
            }
            if (lane == 0) {
                const float mu  = s * (1.f / DD);
                const float var = s2 * (1.f / DD) - mu * mu;
                s_mu   = mu;
                s_rstd = rsqrtf(var + 1e-5f);
            }
        }
        __syncthreads();
        oh[idx] = __float2half_rn((x - s_mu) * s_rstd * gd + bd);
    }
}

// --------------------------------- launch --------------------------------------
extern "C" void kernel_launch(void* const* d_in, const int* in_sizes, int n_in,
                              void* d_out, int out_size)
{
    const float* x   = (const float*)d_in[0];
    const float* Wk  = (const float*)d_in[1];
    const float* bk  = (const float*)d_in[2];
    const float* Wv  = (const float*)d_in[3];
    const float* bv  = (const float*)d_in[4];
    const float* Wq  = (const float*)d_in[5];
    const float* bq  = (const float*)d_in[6];
    const float* Wkp = (const float*)d_in[7];
    const float* bkp = (const float*)d_in[8];
    const float* Wqp = (const float*)d_in[9];
    const float* bqp = (const float*)d_in[10];
    const float* ps  = (const float*)d_in[11];
    const float* lng = (const float*)d_in[12];
    const float* lnb = (const float*)d_in[13];
    const float* Wo  = (const float*)d_in[14];
    const float* bo  = (const float*)d_in[15];
    float* out = (float*)d_out;

    __half *xh, *lnh;
    __half *wv_h, *wo_h, *wkp_h, *wkp_l, *wqp_h, *wqp_l;
    __half *wkt_h, *wkt_l, *wqt_h, *wqt_l, *wck_h, *wcq_h;
    float *val, *kpv, *qpv, *bck, *bcq;
    cudaGetSymbolAddress((void**)&xh,    g_xh);
    cudaGetSymbolAddress((void**)&lnh,   g_lnh);
    cudaGetSymbolAddress((void**)&val,   g_val);
    cudaGetSymbolAddress((void**)&kpv,   g_kp);
    cudaGetSymbolAddress((void**)&qpv,   g_qp);
    cudaGetSymbolAddress((void**)&wv_h,  g_wv_h);
    cudaGetSymbolAddress((void**)&wo_h,  g_wo_h);
    cudaGetSymbolAddress((void**)&wkp_h, g_wkp_h);
    cudaGetSymbolAddress((void**)&wkp_l, g_wkp_l);
    cudaGetSymbolAddress((void**)&wqp_h, g_wqp_h);
    cudaGetSymbolAddress((void**)&wqp_l, g_wqp_l);
    cudaGetSymbolAddress((void**)&wkt_h, g_wkt_h);
    cudaGetSymbolAddress((void**)&wkt_l, g_wkt_l);
    cudaGetSymbolAddress((void**)&wqt_h, g_wqt_h);
    cudaGetSymbolAddress((void**)&wqt_l, g_wqt_l);
    cudaGetSymbolAddress((void**)&wck_h, g_wck_h);
    cudaGetSymbolAddress((void**)&wcq_h, g_wcq_h);
    cudaGetSymbolAddress((void**)&bck,   g_bck);
    cudaGetSymbolAddress((void**)&bcq,   g_bcq);

    cudaFuncSetAttribute(gemm1p, cudaFuncAttributeMaxDynamicSharedMemorySize, SMEM_BYTES);
    cudaFuncSetAttribute(gemm3p, cudaFuncAttributeMaxDynamicSharedMemorySize, SMEM3_BYTES);

    // splits: Wv(hi), Wkp(hi+lo), Wqp(hi+lo) | Wo(hi) | x(hi)
    split3<<<dim3(DD * DD / 1024, 3), 256>>>(Wv, Wkp, Wqp,
        wv_h, nullptr, wkp_h, wkp_l, wqp_h, wqp_l);
    split3<<<dim3(DD * DD / 1024, 1), 256>>>(Wo, Wo, Wo,
        wo_h, nullptr, nullptr, nullptr, nullptr, nullptr);
    split3<<<dim3(MB * DD / 1024, 1), 256>>>(x, x, x,
        xh, nullptr, nullptr, nullptr, nullptr, nullptr);
    // transposed splits of Wk, Wq (W-side of the combine)
    tsplit<<<dim3(32, 32, 2), 256>>>(Wk, Wq, wkt_h, wkt_l, wqt_h, wqt_l);
    // combined biases: bck = Wkp*bk + bkp ; bcq = Wqp*bq + bqp
    matvec<<<dim3(DD, 2), 256>>>(Wkp, bk, bkp, Wqp, bq, bqp, bck, bcq);

    // combined weights: Wck = Wkp*Wk, Wcq = Wqp*Wq  (3-pass, hi fp16 out)
    {
        CombArgs a = {};
        a.Ah[0] = wkp_h; a.Al[0] = wkp_l; a.Wh[0] = wkt_h; a.Wl[0] = wkt_l; a.Ch[0] = wck_h;
        a.Ah[1] = wqp_h; a.Al[1] = wqp_l; a.Wh[1] = wqt_h; a.Wl[1] = wqt_l; a.Ch[1] = wcq_h;
        gemm3p<<<dim3(DD / BN, DD / BM, 2), 256, SMEM3_BYTES>>>(a);
    }

    // fused big GEMM: z0 value (mode0), z1 key_phase (mode1), z2 query_phase (mode1)
    {
        GemmArgs a = {};
        a.Ah[0] = a.Ah[1] = a.Ah[2] = xh;
        a.Wh[0] = wv_h;  a.bias[0] = bv;  a.mode[0] = 0; a.Cf[0] = val;
        a.Wh[1] = wck_h; a.bias[1] = bck; a.mode[1] = 1; a.Cf[1] = kpv; a.extra[1] = ps;
        a.Wh[2] = wcq_h; a.bias[2] = bcq; a.mode[2] = 1; a.Cf[2] = qpv; a.extra[2] = ps;
        gemm1p<<<dim3(DD / BN, MB / BM, 3), 256, SMEM_BYTES>>>(a);
    }
    // bind + chunked cumsum + retrieve + layernorm -> hi fp16
    scan_ln<<<MB / CHUNK, 1024>>>(val, kpv, qpv, lng, lnb, lnh);
    // output projection + residual
    {
        GemmArgs a = {};
        a.Ah[0] = lnh; a.Wh[0] = wo_h; a.bias[0] = bo;
        a.mode[0] = 2; a.extra[0] = x; a.Cf[0] = out;
        gemm1p<<<dim3(DD / BN, MB / BM, 1), 256, SMEM_BYTES>>>(a);
    }
}